// round 13
// baseline (speedup 1.0000x reference)
#include <cuda_runtime.h>
#include <cuda_bf16.h>
#include <math.h>

// Problem constants
#define BATCH 8
#define NSTMT 80
#define NNODE 81
#define HID   256
#define H4    1024
#define NSTEP 8
#define VOCAB 30000
#define CHAINS (NNODE*BATCH)   // 648
#define NGROUPS 20             // active 32-row groups (rows 640..647 never active)
#define GSZ 8                  // CTAs per row-group (each handles 2 column tiles)

#define ASTR 40   // mma smem A row stride (bf16)
#define BSTR 72   // mma smem B row stride

// ---------------- device scratch (allocation-free) ----------------
static __device__ float d_SKIP[BATCH*NNODE*NNODE*HID];   // [b][start][pos][h]
static __device__ float d_KEYS[BATCH*NNODE*NNODE*HID];
static __device__ float d_STMT[BATCH*NSTMT*HID];
static __device__ float d_TMPH[BATCH*NSTMT*HID];
static __device__ float d_XG0 [BATCH*NSTMT*H4];          // stmt@skWx0 + skb0 (interleaved)
// ping-pong raw skip-LSTM state
static __device__ float d_RC0[2*CHAINS*HID];
static __device__ float d_RH0[2*CHAINS*HID];
static __device__ float d_RC1[2*CHAINS*HID];
static __device__ float d_RH1[2*CHAINS*HID];
// deterministic per-(row, col-tile) partial sums of raw concat state: (sum, sumsq)
static __device__ float2 d_PSA[2][CHAINS][16];   // from phase A (c0,h0)
static __device__ float2 d_PSB[2][CHAINS][16];   // from phase B (c1,h1)
static __device__ float d_HC [CHAINS*H4];   // exec state: c0,h0,c1,h1
static __device__ float d_QP [4][CHAINS*HID];    // K-split Q partials
static __device__ float d_T  [BATCH*NNODE*NNODE];
static __device__ float d_P  [CHAINS];
static __device__ float d_XHE[CHAINS*512];  // [x_in, h0prop]
static __device__ float d_XH2[CHAINS*512];  // [h0new, h1prop]
static __device__ float d_CPR[CHAINS*512];  // [c0prop, c1prop]
// bf16 hi/lo split weights (hi at [0], lo at [K*N]); all gate-interleaved where applicable
static __device__ __nv_bfloat16 d_ST0w [2*HID*H4];
static __device__ __nv_bfloat16 d_ST1w [2*HID*H4];
static __device__ __nv_bfloat16 d_SKX0w[2*HID*H4];
static __device__ __nv_bfloat16 d_SKH0w[2*HID*H4];   // skip L0 recurrent
static __device__ __nv_bfloat16 d_SK1w [2*512*H4];   // skip L1 [Wx1;Wh1]
static __device__ __nv_bfloat16 d_EX0w [2*512*H4];   // [exWx0; exWh0]
static __device__ __nv_bfloat16 d_EX1w [2*512*H4];   // [exWx1; exWh1]
static __device__ __nv_bfloat16 d_WSw  [2*HID*HID];  // keys
static __device__ float d_BST0[H4], d_BST1[H4], d_BSK0[H4], d_BSK1[H4], d_BEX0[H4], d_BEX1[H4];
// per-row-group barrier state (own cache line per group)
static __device__ unsigned g_gcnt[NGROUPS*32];
static __device__ unsigned g_ggen[NGROUPS*32];

// ---------------- helpers ----------------
// Guaranteed fast-math paths (MUFU-based) regardless of compiler flags.
__device__ __forceinline__ float sigf(float x){
    return __fdividef(1.f, 1.f + __expf(-x));
}
__device__ __forceinline__ float ftanh(float x){
    return 1.f - __fdividef(2.f, __expf(2.f*x) + 1.f);
}

// 8-CTA row-group barrier: all CTAs of a group are co-resident (single wave).
__device__ __forceinline__ void group_barrier(int grp) {
    __syncthreads();
    if (threadIdx.x == 0) {
        unsigned gen = *(volatile unsigned*)&g_ggen[grp*32];
        __threadfence();
        if (atomicAdd(&g_gcnt[grp*32], 1u) == (unsigned)(GSZ - 1)) {
            atomicExch(&g_gcnt[grp*32], 0u);
            __threadfence();
            atomicExch(&g_ggen[grp*32], gen + 1u);
        } else {
            while (*(volatile unsigned*)&g_ggen[grp*32] == gen) { __nanosleep(32); }
        }
        __threadfence();
    }
    __syncthreads();
}

__device__ __forceinline__ void store_hl(__nv_bfloat16* base, int total, int i, float v) {
    __nv_bfloat16 h = __float2bfloat16(v);
    base[i] = h;
    base[total + i] = __float2bfloat16(v - __bfloat162float(h));
}
__device__ __forceinline__ unsigned pack_hl(float x0, float x1, unsigned& lo_out) {
    __nv_bfloat16 h0 = __float2bfloat16(x0);
    __nv_bfloat16 h1 = __float2bfloat16(x1);
    __nv_bfloat16 l0 = __float2bfloat16(x0 - __bfloat162float(h0));
    __nv_bfloat16 l1 = __float2bfloat16(x1 - __bfloat162float(h1));
    unsigned uh = (unsigned)__bfloat16_as_ushort(h0) | ((unsigned)__bfloat16_as_ushort(h1) << 16);
    lo_out      = (unsigned)__bfloat16_as_ushort(l0) | ((unsigned)__bfloat16_as_ushort(l1) << 16);
    return uh;
}
__device__ __forceinline__ void ldsm_x4(unsigned* r, const __nv_bfloat16* p) {
    unsigned addr = (unsigned)__cvta_generic_to_shared(p);
    asm volatile("ldmatrix.sync.aligned.m8n8.x4.shared.b16 {%0,%1,%2,%3}, [%4];"
        : "=r"(r[0]), "=r"(r[1]), "=r"(r[2]), "=r"(r[3]) : "r"(addr));
}
__device__ __forceinline__ void ldsm_x4_t(unsigned* r, const __nv_bfloat16* p) {
    unsigned addr = (unsigned)__cvta_generic_to_shared(p);
    asm volatile("ldmatrix.sync.aligned.m8n8.x4.trans.shared.b16 {%0,%1,%2,%3}, [%4];"
        : "=r"(r[0]), "=r"(r[1]), "=r"(r[2]), "=r"(r[3]) : "r"(addr));
}
__device__ __forceinline__ void mma_bf16(float* c, const unsigned* a, const unsigned* b) {
    asm volatile("mma.sync.aligned.m16n8k16.row.col.f32.bf16.bf16.f32 "
        "{%0,%1,%2,%3}, {%4,%5,%6,%7}, {%8,%9}, {%0,%1,%2,%3};"
        : "+f"(c[0]), "+f"(c[1]), "+f"(c[2]), "+f"(c[3])
        : "r"(a[0]), "r"(a[1]), "r"(a[2]), "r"(a[3]), "r"(b[0]), "r"(b[1]));
}

// ---------------- init / weight prep ----------------
__global__ void init_kernel() {
    int stride = gridDim.x * blockDim.x;
    int gid = blockIdx.x * blockDim.x + threadIdx.x;
    // d_SKIP's never-written region stays 0 from module init (validated R7/R9/R10/R11/R12).
    for (int i = gid; i < CHAINS*H4; i += stride) d_HC[i] = 0.f;
    for (int i = gid; i < CHAINS; i += stride) d_P[i] = (i % NNODE == 0) ? 1.f : 0.f;
    if (gid < NGROUPS*32) { g_gcnt[gid] = 0u; g_ggen[gid] = 0u; }
}

__global__ void build_w(const float* __restrict__ stWx, const float* __restrict__ skWx,
                        const float* __restrict__ skWh, const float* __restrict__ exWx,
                        const float* __restrict__ exWh, const float* __restrict__ ws) {
    int i = blockIdx.x*256 + threadIdx.x;
    if (i >= 512*H4) return;
    int k = i >> 10, n = i & 1023;
    int h = n >> 2, g = n & 3;
    int sc = h + 256*g;                 // source (non-interleaved) column
    const int L1 = 256*H4;
    float v;
    v = (k < 256) ? skWx[L1 + k*H4 + sc] : skWh[L1 + (k-256)*H4 + sc];
    store_hl(d_SK1w, 512*H4, i, v);
    v = (k < 256) ? exWx[k*H4 + sc]      : exWh[(k-256)*H4 + sc];
    store_hl(d_EX0w, 512*H4, i, v);
    v = (k < 256) ? exWx[L1 + k*H4 + sc] : exWh[L1 + (k-256)*H4 + sc];
    store_hl(d_EX1w, 512*H4, i, v);
    if (k < 256) {
        int j = k*H4 + n;
        store_hl(d_ST0w,  HID*H4, j, stWx[k*H4 + sc]);
        store_hl(d_ST1w,  HID*H4, j, stWx[L1 + k*H4 + sc]);
        store_hl(d_SKX0w, HID*H4, j, skWx[k*H4 + sc]);
        store_hl(d_SKH0w, HID*H4, j, skWh[k*H4 + sc]);
    }
    if (i < HID*HID) store_hl(d_WSw, HID*HID, i, ws[i]);
}

__global__ void build_b(const float* __restrict__ st_b, const float* __restrict__ sk_b,
                        const float* __restrict__ ex_b) {
    int i = blockIdx.x*256 + threadIdx.x;
    if (i >= H4) return;
    int h = i >> 2, g = i & 3;
    int sc = h + 256*g;
    d_BST0[i] = st_b[sc];       d_BST1[i] = st_b[H4 + sc];
    d_BSK0[i] = sk_b[sc];       d_BSK1[i] = sk_b[H4 + sc];
    d_BEX0[i] = ex_b[sc];       d_BEX1[i] = ex_b[H4 + sc];
}

// ---------------- launch-path tensor-core GEMM + fused LSTM epilogues ----------------
// C/out = A[M x (NC*32)] @ B[(NC*32) x 1024] (+interleaved bias).
// 32x64 tile, 128 threads, bf16 hi/lo 3-pass. Fragment layout identical to skip_tile.
// EPI: 0 plain store(+bias), 1 stmt zero-carry cell, 4 exec L0, 5 exec L1
template<int EPI, int NC>
__global__ void __launch_bounds__(128) gemm_mma_epi(
    const float* __restrict__ A, const __nv_bfloat16* __restrict__ Bh_g,
    const float* __restrict__ bias, float* __restrict__ C,
    int M, float* __restrict__ p1, float* __restrict__ p2, float* __restrict__ p3)
{
    const int K = NC << 5;
    const __nv_bfloat16* Bl_g = Bh_g + (size_t)K*H4;
    __shared__ __align__(16) __nv_bfloat16 sAh[2][32*ASTR];
    __shared__ __align__(16) __nv_bfloat16 sAl[2][32*ASTR];
    __shared__ __align__(16) __nv_bfloat16 sBh[2][32*BSTR];
    __shared__ __align__(16) __nv_bfloat16 sBl[2][32*BSTR];
    const int tid = threadIdx.x;
    const int lane = tid & 31, wid = tid >> 5;
    const int wr = wid >> 1, wc = wid & 1;
    const int row0 = blockIdx.y << 5;
    const int col0 = blockIdx.x << 6;
    const int arow = tid >> 2, acol = (tid & 3) << 3;
    const int brow = tid >> 2, bcol = (tid & 3) << 4;
    const int gA = row0 + arow;
    const bool av = gA < M;
    const float* Arow = A + (size_t)gA*K;

    float4 ra0, ra1;
    uint4 wh0, wh1, wl0, wl1;

    #define LOADC(c) do {                                                         \
        int k0_ = (c) << 5;                                                       \
        if (av) {                                                                 \
            ra0 = *(const float4*)(Arow + k0_ + acol);                            \
            ra1 = *(const float4*)(Arow + k0_ + acol + 4);                        \
        } else { ra0 = make_float4(0.f,0.f,0.f,0.f); ra1 = ra0; }                 \
        size_t off_ = (size_t)(k0_ + brow)*H4 + col0 + bcol;                      \
        wh0 = *(const uint4*)(Bh_g + off_); wh1 = *(const uint4*)(Bh_g + off_ + 8); \
        wl0 = *(const uint4*)(Bl_g + off_); wl1 = *(const uint4*)(Bl_g + off_ + 8); \
    } while(0)

    #define STOREC(buf) do {                                                      \
        float v_[8] = {ra0.x, ra0.y, ra0.z, ra0.w, ra1.x, ra1.y, ra1.z, ra1.w};   \
        _Pragma("unroll")                                                         \
        for (int e_ = 0; e_ < 4; e_++) {                                          \
            unsigned ul_;                                                         \
            unsigned uh_ = pack_hl(v_[2*e_], v_[2*e_+1], ul_);                    \
            *reinterpret_cast<unsigned*>(&sAh[buf][arow*ASTR + acol + 2*e_]) = uh_; \
            *reinterpret_cast<unsigned*>(&sAl[buf][arow*ASTR + acol + 2*e_]) = ul_; \
        }                                                                         \
        *(uint4*)&sBh[buf][brow*BSTR + bcol] = wh0;                               \
        *(uint4*)&sBh[buf][brow*BSTR + bcol + 8] = wh1;                           \
        *(uint4*)&sBl[buf][brow*BSTR + bcol] = wl0;                               \
        *(uint4*)&sBl[buf][brow*BSTR + bcol + 8] = wl1;                           \
    } while(0)

    float acc[4][4];
    #pragma unroll
    for (int a = 0; a < 4; a++)
        #pragma unroll
        for (int b = 0; b < 4; b++) acc[a][b] = 0.f;

    LOADC(0); STOREC(0);
    __syncthreads();
    for (int c = 0; c < NC; c++) {
        const int p = c & 1;
        if (c + 1 < NC) LOADC(c + 1);
        #pragma unroll
        for (int kk = 0; kk < 2; kk++) {
            unsigned ah[4], al[4], bh[2][4], bl[2][4];
            const int kc = (kk << 4) + ((lane >> 4) << 3);
            const int r_ = wr*16 + (lane & 15);
            ldsm_x4(ah, &sAh[p][r_*ASTR + kc]);
            ldsm_x4(al, &sAl[p][r_*ASTR + kc]);
            const int kr = (kk << 4) + (lane & 15);
            #pragma unroll
            for (int g2 = 0; g2 < 2; g2++) {
                int nc_ = wc*32 + g2*16 + ((lane >> 4) << 3);
                ldsm_x4_t(bh[g2], &sBh[p][kr*BSTR + nc_]);
                ldsm_x4_t(bl[g2], &sBl[p][kr*BSTR + nc_]);
            }
            #pragma unroll
            for (int nf = 0; nf < 4; nf++) {
                const unsigned* pbh = &bh[nf>>1][(nf&1)<<1];
                const unsigned* pbl = &bl[nf>>1][(nf&1)<<1];
                mma_bf16(acc[nf], ah, pbh);
                mma_bf16(acc[nf], al, pbh);
                mma_bf16(acc[nf], ah, pbl);
            }
        }
        if (c + 1 < NC) {
            STOREC(p ^ 1);
            __syncthreads();
        }
    }
    #undef LOADC
    #undef STOREC

    const int gm0 = row0 + wr*16 + (lane >> 2);
    if (EPI == 0) {
        #pragma unroll
        for (int nf = 0; nf < 4; nf++) {
            int colb = col0 + wc*32 + nf*8 + ((lane & 3) << 1);
            float b0 = bias[colb], b1 = bias[colb+1];
            if (gm0 < M)
                *(float2*)&C[(size_t)gm0*H4 + colb] =
                    make_float2(acc[nf][0]+b0, acc[nf][1]+b1);
            if (gm0+8 < M)
                *(float2*)&C[(size_t)(gm0+8)*H4 + colb] =
                    make_float2(acc[nf][2]+b0, acc[nf][3]+b1);
        }
    } else {
        #pragma unroll
        for (int nf = 0; nf < 4; nf++) {
            float v0 = acc[nf][0], v1 = acc[nf][1], v2 = acc[nf][2], v3 = acc[nf][3];
            float s0 = __shfl_xor_sync(0xffffffffu, v0, 1);
            float s1 = __shfl_xor_sync(0xffffffffu, v1, 1);
            float s2 = __shfl_xor_sync(0xffffffffu, v2, 1);
            float s3 = __shfl_xor_sync(0xffffffffu, v3, 1);
            if (!(lane & 1)) {
                int colb = col0 + wc*32 + nf*8 + ((lane & 3) << 1);
                int u = colb >> 2;
                float4 bv = *(const float4*)&bias[u<<2];
                #pragma unroll
                for (int rr = 0; rr < 2; rr++) {
                    int gm = gm0 + rr*8;
                    if (gm >= M) continue;
                    float gi = (rr ? v2 : v0) + bv.x;
                    float gf = (rr ? v3 : v1) + bv.y;
                    float gg = (rr ? s2 : s0) + bv.z;
                    float go = (rr ? s3 : s1) + bv.w;
                    if (EPI == 1) {
                        float cv = sigf(gi)*ftanh(gg);
                        p1[gm*HID + u] = sigf(go)*ftanh(cv);
                    } else if (EPI == 4) {
                        float cp = p1[gm*512 + u];    // c0 prop
                        float cv = sigf(gf)*cp + sigf(gi)*ftanh(gg);
                        float hv = sigf(go)*ftanh(cv);
                        p2[(size_t)gm*H4 + u]       = cv;
                        p2[(size_t)gm*H4 + HID + u] = hv;
                        p3[gm*512 + u]              = hv;
                    } else {
                        float cp = p1[gm*512 + HID + u];  // c1 prop
                        float cv = sigf(gf)*cp + sigf(gi)*ftanh(gg);
                        float hv = sigf(go)*ftanh(cv);
                        p2[(size_t)gm*H4 + 512 + u] = cv;
                        p2[(size_t)gm*H4 + 768 + u] = hv;
                    }
                }
            }
        }
    }
}

// ---------------- K-split Q GEMM (fp32; unchanged) ----------------
__global__ void __launch_bounds__(128) gemm_qk(const float* __restrict__ wk) {
    __shared__ float As[2][16][36];
    __shared__ float Bs[2][16][64];
    const int tid = threadIdx.x;
    const int tx = tid & 15, ty = tid >> 4;
    const int row0 = blockIdx.y * 32;
    const int col0 = blockIdx.x * 64;
    const int ks = blockIdx.z;
    const int kofs = ks << 8;
    const int am = tid >> 2;
    const int ak = (tid & 3) << 2;
    const int bk = tid >> 4;
    const int bn = (tid & 15) << 2;
    const int gmA = row0 + am;
    const bool av = gmA < CHAINS;
    float acc[4][4] = {};
    float4 ra, rb0, rb1;
    ra = av ? *(const float4*)&d_HC[(size_t)gmA*H4 + kofs + ak] : make_float4(0.f,0.f,0.f,0.f);
    rb0 = *(const float4*)&wk[(size_t)(kofs+bk)*HID + col0 + bn];
    rb1 = *(const float4*)&wk[(size_t)(kofs+bk+8)*HID + col0 + bn];
    As[0][ak][am]=ra.x; As[0][ak+1][am]=ra.y; As[0][ak+2][am]=ra.z; As[0][ak+3][am]=ra.w;
    *(float4*)&Bs[0][bk][bn] = rb0;
    *(float4*)&Bs[0][bk+8][bn] = rb1;
    __syncthreads();
    for (int t = 0; t < 16; t++) {
        const int p = t & 1;
        if (t+1 < 16) {
            int k0 = (t+1) << 4;
            ra = av ? *(const float4*)&d_HC[(size_t)gmA*H4 + kofs + k0 + ak] : make_float4(0.f,0.f,0.f,0.f);
            rb0 = *(const float4*)&wk[(size_t)(kofs+k0+bk)*HID + col0 + bn];
            rb1 = *(const float4*)&wk[(size_t)(kofs+k0+bk+8)*HID + col0 + bn];
        }
        #pragma unroll
        for (int kk = 0; kk < 16; kk++) {
            float4 b4 = *(const float4*)&Bs[p][kk][tx<<2];
            float4 a4 = *(const float4*)&As[p][kk][ty<<2];
            acc[0][0]+=a4.x*b4.x; acc[0][1]+=a4.x*b4.y; acc[0][2]+=a4.x*b4.z; acc[0][3]+=a4.x*b4.w;
            acc[1][0]+=a4.y*b4.x; acc[1][1]+=a4.y*b4.y; acc[1][2]+=a4.y*b4.z; acc[1][3]+=a4.y*b4.w;
            acc[2][0]+=a4.z*b4.x; acc[2][1]+=a4.z*b4.y; acc[2][2]+=a4.z*b4.z; acc[2][3]+=a4.z*b4.w;
            acc[3][0]+=a4.w*b4.x; acc[3][1]+=a4.w*b4.y; acc[3][2]+=a4.w*b4.z; acc[3][3]+=a4.w*b4.w;
        }
        if (t+1 < 16) {
            const int q = p ^ 1;
            As[q][ak][am]=ra.x; As[q][ak+1][am]=ra.y; As[q][ak+2][am]=ra.z; As[q][ak+3][am]=ra.w;
            *(float4*)&Bs[q][bk][bn] = rb0;
            *(float4*)&Bs[q][bk+8][bn] = rb1;
            __syncthreads();
        }
    }
    #pragma unroll
    for (int i = 0; i < 4; i++) {
        int gm = row0 + (ty<<2) + i;
        if (gm >= CHAINS) continue;
        *(float4*)&d_QP[ks][(size_t)gm*HID + col0 + (tx<<2)] =
            make_float4(acc[i][0], acc[i][1], acc[i][2], acc[i][3]);
    }
}

// ---------------- persistent skip encoder (row-group clusters, local barriers) -------
struct PSmem {
    __nv_bfloat16 Ah[2][32*ASTR];
    __nv_bfloat16 Al[2][32*ASTR];
    __nv_bfloat16 Bh[2][32*BSTR];
    __nv_bfloat16 Bl[2][32*BSTR];
    float lns[1024], lnb[1024];
    float mu[32], rs[32];
    float2 ps[32][2];
};

template<int PHASE>
__device__ __forceinline__ void skip_tile(
    PSmem& sm, int t, int idx, int actlim, int M, int prv, int cur,
    const float* __restrict__ rh_prev,
    const float* __restrict__ rc_prev,
    const float* __restrict__ rh0_cur,
    float* __restrict__ rc_out, float* __restrict__ rh_out,
    const __nv_bfloat16* __restrict__ WBh, const __nv_bfloat16* __restrict__ WBl)
{
    const int tid = threadIdx.x;
    const int lane = tid & 31, wid = tid >> 5;
    const int wr = wid >> 1, wc = wid & 1;
    const int rt = t >> 4, ct = t & 15;
    const int row0 = rt << 5, col0 = ct << 6;

    const int NC = (PHASE == 0) ? 8 : 16;
    const int arow = tid >> 2, acol = (tid & 3) << 3;
    const int brow = tid >> 2, bcol = (tid & 3) << 4;
    const int gA = row0 + arow;

    float4 rA0_0, rA1_0, rA0_1, rA1_1;
    uint4 rwh0_0, rwh1_0, rwl0_0, rwl1_0;
    uint4 rwh0_1, rwh1_1, rwl0_1, rwl1_1;
    bool act_0 = false, lnf_0 = false, act_1 = false, lnf_1 = false;
    int kb_0 = 0, kb_1 = 0;

    #define LOAD_AB(c, S) do {                                                    \
        int k0_ = (c) << 5;                                                       \
        const float* src_; bool a_; bool l_; int kk0_;                            \
        if (PHASE == 0) { src_ = rh_prev; a_ = (gA < actlim); l_ = true; kk0_ = k0_; } \
        else if (k0_ < 256) { src_ = rh0_cur; a_ = (gA < M); l_ = false; kk0_ = k0_; } \
        else { src_ = rh_prev; a_ = (gA < actlim); l_ = true; kk0_ = k0_ - 256; } \
        act_##S = a_; lnf_##S = l_; kb_##S = kk0_ + acol;                         \
        if (a_) {                                                                 \
            rA0_##S = __ldcg((const float4*)(src_ + (size_t)gA*HID + kk0_ + acol));     \
            rA1_##S = __ldcg((const float4*)(src_ + (size_t)gA*HID + kk0_ + acol + 4)); \
        } else { rA0_##S = make_float4(0.f,0.f,0.f,0.f); rA1_##S = rA0_##S; }     \
        size_t off_ = (size_t)(k0_ + brow)*H4 + col0 + bcol;                      \
        rwh0_##S = *(const uint4*)(WBh + off_); rwh1_##S = *(const uint4*)(WBh + off_ + 8); \
        rwl0_##S = *(const uint4*)(WBl + off_); rwl1_##S = *(const uint4*)(WBl + off_ + 8); \
    } while(0)

    #define STORE_AB(S, BUF) do {                                                 \
        float v_[8] = {rA0_##S.x, rA0_##S.y, rA0_##S.z, rA0_##S.w,                \
                       rA1_##S.x, rA1_##S.y, rA1_##S.z, rA1_##S.w};               \
        if (act_##S && lnf_##S) {                                                 \
            const int lo_ = (PHASE == 0) ? 256 : 768;                             \
            _Pragma("unroll")                                                     \
            for (int e_ = 0; e_ < 8; e_++)                                        \
                v_[e_] = (v_[e_] - muA)*rsA*sm.lns[lo_ + kb_##S + e_] + sm.lnb[lo_ + kb_##S + e_]; \
        }                                                                         \
        _Pragma("unroll")                                                         \
        for (int e_ = 0; e_ < 4; e_++) {                                          \
            unsigned ul_;                                                         \
            unsigned uh_ = pack_hl(v_[2*e_], v_[2*e_+1], ul_);                    \
            *reinterpret_cast<unsigned*>(&sm.Ah[BUF][arow*ASTR + acol + 2*e_]) = uh_; \
            *reinterpret_cast<unsigned*>(&sm.Al[BUF][arow*ASTR + acol + 2*e_]) = ul_; \
        }                                                                         \
        *(uint4*)&sm.Bh[BUF][brow*BSTR + bcol] = rwh0_##S;                        \
        *(uint4*)&sm.Bh[BUF][brow*BSTR + bcol + 8] = rwh1_##S;                    \
        *(uint4*)&sm.Bl[BUF][brow*BSTR + bcol] = rwl0_##S;                        \
        *(uint4*)&sm.Bl[BUF][brow*BSTR + bcol + 8] = rwl1_##S;                    \
    } while(0)

    #define COMPUTE(BUF) do {                                                     \
        _Pragma("unroll")                                                         \
        for (int kk = 0; kk < 2; kk++) {                                          \
            unsigned ah[4], al[4], bh[2][4], bl[2][4];                            \
            const int kc = (kk << 4) + ((lane >> 4) << 3);                        \
            const int r_ = wr*16 + (lane & 15);                                   \
            ldsm_x4(ah, &sm.Ah[BUF][r_*ASTR + kc]);                               \
            ldsm_x4(al, &sm.Al[BUF][r_*ASTR + kc]);                               \
            const int kr = (kk << 4) + (lane & 15);                               \
            _Pragma("unroll")                                                     \
            for (int g2 = 0; g2 < 2; g2++) {                                      \
                int nc_ = wc*32 + g2*16 + ((lane >> 4) << 3);                     \
                ldsm_x4_t(bh[g2], &sm.Bh[BUF][kr*BSTR + nc_]);                    \
                ldsm_x4_t(bl[g2], &sm.Bl[BUF][kr*BSTR + nc_]);                    \
            }                                                                     \
            _Pragma("unroll")                                                     \
            for (int nf = 0; nf < 4; nf++) {                                      \
                const unsigned* pbh = &bh[nf>>1][(nf&1)<<1];                      \
                const unsigned* pbl = &bl[nf>>1][(nf&1)<<1];                      \
                mma_bf16(acc[nf], ah, pbh);                                       \
                mma_bf16(acc[nf], al, pbh);                                       \
                mma_bf16(acc[nf], ah, pbl);                                       \
            }                                                                     \
        }                                                                         \
    } while(0)

    LOAD_AB(0, 0);

    float cpr[2][4];
    const int gm0 = row0 + wr*16 + (lane >> 2);
    #pragma unroll
    for (int rr = 0; rr < 2; rr++)
        #pragma unroll
        for (int nf = 0; nf < 4; nf++) {
            int colb = col0 + wc*32 + nf*8 + ((lane & 3) << 1);
            int u = colb >> 2;
            int gm = gm0 + rr*8;
            cpr[rr][nf] = (gm < actlim) ? __ldcg(rc_prev + (size_t)gm*HID + u) : 0.f;
        }

    {
        int rr = tid >> 2, q = tid & 3;
        int gm = row0 + rr;
        float s = 0.f, s2 = 0.f;
        if (gm < actlim) {
            #pragma unroll
            for (int e = 0; e < 8; e++) {
                int slot = q*8 + e;
                float2 v = (slot < 16) ? __ldcg(&d_PSA[prv][gm][slot])
                                       : __ldcg(&d_PSB[prv][gm][slot-16]);
                s += v.x; s2 += v.y;
            }
        }
        s  += __shfl_xor_sync(0xffffffffu, s, 1);
        s  += __shfl_xor_sync(0xffffffffu, s, 2);
        s2 += __shfl_xor_sync(0xffffffffu, s2, 1);
        s2 += __shfl_xor_sync(0xffffffffu, s2, 2);
        if (q == 0) {
            float mu = s * (1.f/1024.f);
            float var = fmaxf(s2 * (1.f/1024.f) - mu*mu, 0.f);
            sm.mu[rr] = mu;
            sm.rs[rr] = rsqrtf(var + 1e-6f);
        }
    }
    __syncthreads();
    const float muA = sm.mu[arow], rsA = sm.rs[arow];

    float acc[4][4];
    #pragma unroll
    for (int a = 0; a < 4; a++)
        #pragma unroll
        for (int b = 0; b < 4; b++) acc[a][b] = 0.f;

    STORE_AB(0, 0);
    LOAD_AB(1, 1);
    __syncthreads();
    for (int c = 0; c < NC; c += 2) {
        if (c + 2 < NC) LOAD_AB(c + 2, 0);
        COMPUTE(0);
        STORE_AB(1, 1);
        __syncthreads();
        if (c + 3 < NC) LOAD_AB(c + 3, 1);
        COMPUTE(1);
        if (c + 2 < NC) {
            STORE_AB(0, 0);
            __syncthreads();
        }
    }
    #undef LOAD_AB
    #undef STORE_AB
    #undef COMPUTE

    float pv[2] = {0.f, 0.f}, p2v[2] = {0.f, 0.f};
    #pragma unroll
    for (int nf = 0; nf < 4; nf++) {
        float v0 = acc[nf][0], v1 = acc[nf][1], v2 = acc[nf][2], v3 = acc[nf][3];
        float s0 = __shfl_xor_sync(0xffffffffu, v0, 1);
        float s1 = __shfl_xor_sync(0xffffffffu, v1, 1);
        float s2 = __shfl_xor_sync(0xffffffffu, v2, 1);
        float s3 = __shfl_xor_sync(0xffffffffu, v3, 1);
        if (!(lane & 1)) {
            int colb = col0 + wc*32 + nf*8 + ((lane & 3) << 1);
            int u = colb >> 2;
            #pragma unroll
            for (int rr = 0; rr < 2; rr++) {
                int gm = gm0 + rr*8;
                if (gm < M) {
                    int r = gm - row0;
                    float gi = (rr ? v2 : v0), gf = (rr ? v3 : v1);
                    float gg = (rr ? s2 : s0), go = (rr ? s3 : s1);
                    float cp;
                    if (PHASE == 0) {
                        float4 xv = *(const float4*)&d_XG0[((size_t)(gm & 7)*NSTMT + idx)*H4 + (u<<2)];
                        gi += xv.x; gf += xv.y; gg += xv.z; go += xv.w;
                        cp = (gm < actlim)
                           ? (cpr[rr][nf] - sm.mu[r])*sm.rs[r]*sm.lns[u] + sm.lnb[u] : 0.f;
                    } else {
                        float4 bv = *(const float4*)&d_BSK1[u<<2];
                        gi += bv.x; gf += bv.y; gg += bv.z; go += bv.w;
                        cp = (gm < actlim)
                           ? (cpr[rr][nf] - sm.mu[r])*sm.rs[r]*sm.lns[512+u] + sm.lnb[512+u] : 0.f;
                    }
                    float cv = sigf(gf)*cp + sigf(gi)*ftanh(gg);
                    float hv = sigf(go)*ftanh(cv);
                    rc_out[(size_t)gm*HID + u] = cv;
                    rh_out[(size_t)gm*HID + u] = hv;
                    if (PHASE == 1) {
                        int s = gm >> 3, b = gm & 7;
                        d_SKIP[(((size_t)b*NNODE + s)*NNODE + (idx+1))*HID + u] = hv;
                    }
                    pv[rr]  += cv + hv;
                    p2v[rr] += cv*cv + hv*hv;
                }
            }
        }
    }
    #pragma unroll
    for (int rr = 0; rr < 2; rr++) {
        pv[rr]  += __shfl_xor_sync(0xffffffffu, pv[rr], 2);
        p2v[rr] += __shfl_xor_sync(0xffffffffu, p2v[rr], 2);
        if ((lane & 3) == 0) {
            int rit = wr*16 + (lane >> 2) + rr*8;
            sm.ps[rit][wc] = make_float2(pv[rr], p2v[rr]);
        }
    }
    __syncthreads();
    if (tid < 32) {
        int gm = row0 + tid;
        if (gm < M) {
            float2 a = sm.ps[tid][0], b = sm.ps[tid][1];
            float2 o = make_float2(a.x + b.x, a.y + b.y);
            if (PHASE == 0) d_PSA[cur][gm][ct] = o;
            else            d_PSB[cur][gm][ct] = o;
        }
    }
    __syncthreads();
}

// 20 row-groups x 8 CTAs; each CTA owns 2 column tiles of its group.
// All dependencies are row-local -> only an 8-CTA group barrier per phase.
__global__ void __launch_bounds__(128, 2) skip_persist(
    const float* __restrict__ lns, const float* __restrict__ lnb)
{
    __shared__ __align__(16) PSmem sm;
    const int tid = threadIdx.x;
    for (int i = tid; i < 1024; i += 128) { sm.lns[i] = lns[i]; sm.lnb[i] = lnb[i]; }
    __syncthreads();

    const int grp  = blockIdx.x >> 3;        // row-group 0..19 (rows grp*32..grp*32+31)
    const int rank = blockIdx.x & 7;
    const int ct0  = rank << 1;

    for (int idx = grp << 2; idx < NSTMT; idx++) {
        const int M = (idx + 1) << 3;
        const int actlim = idx << 3;
        const int cur = idx & 1, prv = cur ^ 1;
        const float* rh0p = d_RH0 + prv*CHAINS*HID;
        const float* rc0p = d_RC0 + prv*CHAINS*HID;
        const float* rh1p = d_RH1 + prv*CHAINS*HID;
        const float* rc1p = d_RC1 + prv*CHAINS*HID;
        float* rh0c = d_RH0 + cur*CHAINS*HID;
        float* rc0c = d_RC0 + cur*CHAINS*HID;
        float* rh1c = d_RH1 + cur*CHAINS*HID;
        float* rc1c = d_RC1 + cur*CHAINS*HID;

        skip_tile<0>(sm, (grp << 4) | ct0, idx, actlim, M, prv, cur,
                     rh0p, rc0p, nullptr, rc0c, rh0c,
                     d_SKH0w, d_SKH0w + HID*H4);
        skip_tile<0>(sm, (grp << 4) | (ct0 + 1), idx, actlim, M, prv, cur,
                     rh0p, rc0p, nullptr, rc0c, rh0c,
                     d_SKH0w, d_SKH0w + HID*H4);
        group_barrier(grp);
        skip_tile<1>(sm, (grp << 4) | ct0, idx, actlim, M, prv, cur,
                     rh1p, rc1p, rh0c, rc1c, rh1c,
                     d_SK1w, d_SK1w + 512*H4);
        skip_tile<1>(sm, (grp << 4) | (ct0 + 1), idx, actlim, M, prv, cur,
                     rh1p, rc1p, rh0c, rc1c, rh1c,
                     d_SK1w, d_SK1w + 512*H4);
        group_barrier(grp);
    }
}

// ---------------- tensor-core GEMM for the big keys GEMM (unchanged) ----
__global__ void __launch_bounds__(128) gemm_mma0(
    const float* __restrict__ A, const __nv_bfloat16* __restrict__ Bh_g,
    const float* __restrict__ bias, float* __restrict__ C,
    int M, int K, int N)
{
    const __nv_bfloat16* Bl_g = Bh_g + (size_t)K*N;
    __shared__ __align__(16) __nv_bfloat16 sAh[64*ASTR];
    __shared__ __align__(16) __nv_bfloat16 sAl[64*ASTR];
    __shared__ __align__(16) __nv_bfloat16 sBh[32*BSTR];
    __shared__ __align__(16) __nv_bfloat16 sBl[32*BSTR];

    const int tid  = threadIdx.x;
    const int lane = tid & 31;
    const int wid  = tid >> 5;
    const int wr   = wid >> 1;
    const int wc   = wid & 1;
    const int row0 = blockIdx.y << 6;
    const int col0 = blockIdx.x << 6;

    const int arow = tid >> 1;
    const int akq  = (tid & 1) << 4;
    const bool aval = (row0 + arow) < M;
    const float* Ag = A + (size_t)(row0 + arow)*K + akq;
    const int seg0 = tid << 1;

    float acc[2][4][4];
    #pragma unroll
    for (int a = 0; a < 2; a++)
        #pragma unroll
        for (int b = 0; b < 4; b++)
            #pragma unroll
            for (int cc = 0; cc < 4; cc++) acc[a][b][cc] = 0.f;

    const int NC = K >> 5;
    for (int cidx = 0; cidx < NC; cidx++) {
        const int k0 = cidx << 5;
        float av[16];
        #pragma unroll
        for (int j = 0; j < 4; j++) {
            float4 f = aval ? *(const float4*)(Ag + k0 + 4*j) : make_float4(0.f,0.f,0.f,0.f);
            av[4*j]=f.x; av[4*j+1]=f.y; av[4*j+2]=f.z; av[4*j+3]=f.w;
        }
        uint4 bvh[2], bvl[2];
        #pragma unroll
        for (int s = 0; s < 2; s++) {
            int seg = seg0 + s;
            int krow = seg >> 3, nc = (seg & 7) << 3;
            size_t off = (size_t)(k0 + krow)*N + col0 + nc;
            bvh[s] = *(const uint4*)(Bh_g + off);
            bvl[s] = *(const uint4*)(Bl_g + off);
        }
        __syncthreads();
        #pragma unroll
        for (int e = 0; e < 8; e++) {
            unsigned ul;
            unsigned uh = pack_hl(av[2*e], av[2*e+1], ul);
            *reinterpret_cast<unsigned*>(&sAh[arow*ASTR + akq + 2*e]) = uh;
            *reinterpret_cast<unsigned*>(&sAl[arow*ASTR + akq + 2*e]) = ul;
        }
        #pragma unroll
        for (int s = 0; s < 2; s++) {
            int seg = seg0 + s;
            int krow = seg >> 3, nc = (seg & 7) << 3;
            *reinterpret_cast<uint4*>(&sBh[krow*BSTR + nc]) = bvh[s];
            *reinterpret_cast<uint4*>(&sBl[krow*BSTR + nc]) = bvl[s];
        }
        __syncthreads();
        #pragma unroll
        for (int kk = 0; kk < 2; kk++) {
            unsigned ah[2][4], al[2][4], bh[2][4], bl[2][4];
            const int kc = (kk << 4) + ((lane >> 4) << 3);
            #pragma unroll
            for (int mi = 0; mi < 2; mi++) {
                int r = wr*32 + mi*16 + (lane & 15);
                ldsm_x4(ah[mi], &sAh[r*ASTR + kc]);
                ldsm_x4(al[mi], &sAl[r*ASTR + kc]);
            }
            const int kr = (kk << 4) + (lane & 15);
            #pragma unroll
            for (int g2 = 0; g2 < 2; g2++) {
                int nc = wc*32 + g2*16 + ((lane >> 4) << 3);
                ldsm_x4_t(bh[g2], &sBh[kr*BSTR + nc]);
                ldsm_x4_t(bl[g2], &sBl[kr*BSTR + nc]);
            }
            #pragma unroll
            for (int mi = 0; mi < 2; mi++)
                #pragma unroll
                for (int nf = 0; nf < 4; nf++) {
                    const unsigned* pbh = &bh[nf>>1][(nf&1)<<1];
                    const unsigned* pbl = &bl[nf>>1][(nf&1)<<1];
                    mma_bf16(acc[mi][nf], ah[mi], pbh);
                    mma_bf16(acc[mi][nf], al[mi], pbh);
                    mma_bf16(acc[mi][nf], ah[mi], pbl);
                }
        }
    }

    #pragma unroll
    for (int mi = 0; mi < 2; mi++) {
        int gm0 = row0 + wr*32 + mi*16 + (lane >> 2);
        #pragma unroll
        for (int nf = 0; nf < 4; nf++) {
            int colb = col0 + wc*32 + nf*8 + ((lane & 3) << 1);
            float b0 = bias ? bias[colb] : 0.f;
            float b1 = bias ? bias[colb+1] : 0.f;
            if (gm0 < M) {
                float2 o = make_float2(acc[mi][nf][0]+b0, acc[mi][nf][1]+b1);
                *(float2*)&C[(size_t)gm0*N + colb] = o;
            }
            if (gm0+8 < M) {
                float2 o = make_float2(acc[mi][nf][2]+b0, acc[mi][nf][3]+b1);
                *(float2*)&C[(size_t)(gm0+8)*N + colb] = o;
            }
        }
    }
}

// ---------------- main-loop kernels (launch path; unchanged) ----------------
__global__ void __launch_bounds__(256) attn_kernel(const float* __restrict__ bk,
                                                   const float* __restrict__ w1,
                                                   const float* __restrict__ b1, int step) {
    int bn = blockIdx.x;               // b*81 + n
    int n = bn % NNODE;
    __shared__ float qsh[HID], w1sh[HID], lg[NNODE];
    int tid = threadIdx.x;
    {
        float v = bk[tid];
        #pragma unroll
        for (int ks = 0; ks < 4; ks++) v += d_QP[ks][(size_t)bn*HID + tid];
        qsh[tid] = v;
    }
    w1sh[tid] = w1[tid];
    __syncthreads();
    int w = tid >> 5, lane = tid & 31;
    float b1v = b1[0];
    for (int m = w; m < NNODE; m += 8) {
        bool allowed = (step == 0) ? (m == 1)
                    : ((step == NSTEP-1) ? (m == NNODE-1)
                                         : (m > n || m == NNODE-1));
        float acc = 0.f;
        if (allowed) {
            const float* kr = d_KEYS + ((size_t)bn*NNODE + m)*HID;
            #pragma unroll 4
            for (int h = lane; h < HID; h += 32)
                acc += ftanh(qsh[h] + kr[h]) * w1sh[h];
            #pragma unroll
            for (int o = 16; o; o >>= 1) acc += __shfl_xor_sync(0xffffffffu, acc, o);
        }
        if (lane == 0)
            lg[m] = allowed ? (acc + b1v) : -1e9f;
    }
    __syncthreads();
    if (w == 0) {
        float mx = -1e30f;
        for (int m = lane; m < NNODE; m += 32) mx = fmaxf(mx, lg[m]);
        #pragma unroll
        for (int o = 16; o; o >>= 1) mx = fmaxf(mx, __shfl_xor_sync(0xffffffffu, mx, o));
        float sum = 0.f;
        for (int m = lane; m < NNODE; m += 32) { float e = __expf(lg[m]-mx); lg[m] = e; sum += e; }
        #pragma unroll
        for (int o = 16; o; o >>= 1) sum += __shfl_xor_sync(0xffffffffu, sum, o);
        float scale = __fdividef(d_P[bn], sum);
        for (int m = lane; m < NNODE; m += 32) d_T[bn*NNODE + m] = lg[m]*scale;
    }
}

__global__ void __launch_bounds__(256) props_kernel() {
    int bm = blockIdx.x;
    int b = bm / NNODE, m = bm % NNODE;
    __shared__ float tsh[NNODE];
    int tid = threadIdx.x;
    if (tid < NNODE) tsh[tid] = d_T[(b*NNODE+tid)*NNODE + m];
    __syncthreads();
    float s = 0.f;
    for (int n = 0; n < NNODE; n++) s += tsh[n];
    float inv = __fdividef(1.f, s + 1e-7f);
    float ax=0.f, a0=0.f, a1=0.f, a2=0.f, a3=0.f;
    int nlim = (m == NNODE-1) ? NNODE : m;
    for (int n = 0; n < nlim; n++) {
        float tv = tsh[n];
        if (tv == 0.f) continue;
        const float* sr = d_SKIP + (((size_t)b*NNODE+n)*NNODE + m)*HID;
        const float* hr = d_HC + (size_t)(b*NNODE+n)*H4;
        ax += tv*sr[tid];
        a0 += tv*hr[tid];      a1 += tv*hr[256+tid];
        a2 += tv*hr[512+tid];  a3 += tv*hr[768+tid];
    }
    d_XHE[bm*512 + tid]       = ax*inv;  // x_in
    d_CPR[bm*512 + tid]       = a0*inv;  // c0 prop
    d_XHE[bm*512 + 256 + tid] = a1*inv;  // h0 prop
    d_CPR[bm*512 + 256 + tid] = a2*inv;  // c1 prop
    d_XH2[bm*512 + 256 + tid] = a3*inv;  // h1 prop
    if (tid == 0) d_P[bm] = s;
}

// ---------------- output projection ----------------
__global__ void __launch_bounds__(256) out_kernel(const int* __restrict__ exit_idx,
                                                  const float* __restrict__ wo,
                                                  const float* __restrict__ bo,
                                                  float* __restrict__ out) {
    __shared__ float hex[BATCH][HID];
    int tid = threadIdx.x;
    for (int i = tid; i < BATCH*HID; i += 256) {
        int b = i >> 8, h = i & 255;
        hex[b][h] = d_HC[(size_t)(b*NNODE + exit_idx[b])*H4 + 768 + h];
    }
    __syncthreads();
    int col = blockIdx.x*256 + tid;
    if (col >= VOCAB) return;
    float acc[BATCH];
    #pragma unroll
    for (int b = 0; b < BATCH; b++) acc[b] = 0.f;
    for (int h = 0; h < HID; h++) {
        float wv = wo[(size_t)h*VOCAB + col];
        #pragma unroll
        for (int b = 0; b < BATCH; b++) acc[b] += hex[b][h]*wv;
    }
    float bv = bo[col];
    #pragma unroll
    for (int b = 0; b < BATCH; b++) out[b*VOCAB + col] = acc[b] + bv;
}

// ---------------- host ----------------
static inline float* sym(const void* s) {
    void* p = nullptr;
    cudaGetSymbolAddress(&p, s);
    return (float*)p;
}
static inline __nv_bfloat16* symb(const void* s) {
    void* p = nullptr;
    cudaGetSymbolAddress(&p, s);
    return (__nv_bfloat16*)p;
}

extern "C" void kernel_launch(void* const* d_in, const int* in_sizes, int n_in,
                              void* d_out, int out_size) {
    const float* node_emb = (const float*)d_in[0];
    const int*   exit_idx = (const int*)  d_in[10];
    const float* st_Wx = (const float*)d_in[12];
    const float* st_b  = (const float*)d_in[14];
    const float* sk_Wx = (const float*)d_in[15];
    const float* sk_Wh = (const float*)d_in[16];
    const float* sk_b  = (const float*)d_in[17];
    const float* ln_s  = (const float*)d_in[18];
    const float* ln_b  = (const float*)d_in[19];
    const float* ex_Wx = (const float*)d_in[20];
    const float* ex_Wh = (const float*)d_in[21];
    const float* ex_b  = (const float*)d_in[22];
    const float* wk = (const float*)d_in[23];
    const float* bk = (const float*)d_in[24];
    const float* ws = (const float*)d_in[25];
    const float* bs = (const float*)d_in[26];
    const float* w1 = (const float*)d_in[27];
    const float* b1 = (const float*)d_in[28];
    const float* wo = (const float*)d_in[29];
    const float* bo = (const float*)d_in[30];
    float* out = (float*)d_out;

    float* pSTMT = sym(d_STMT);
    float* pTMPH = sym(d_TMPH);
    float* pXG0  = sym(d_XG0);
    float* pSKIP = sym(d_SKIP);
    float* pKEYS = sym(d_KEYS);
    float* pHC   = sym(d_HC);
    float* pXHE  = sym(d_XHE);
    float* pXH2  = sym(d_XH2);
    float* pCPR  = sym(d_CPR);
    __nv_bfloat16* pST0w  = symb(d_ST0w);
    __nv_bfloat16* pST1w  = symb(d_ST1w);
    __nv_bfloat16* pSKX0w = symb(d_SKX0w);
    __nv_bfloat16* pEX0w  = symb(d_EX0w);
    __nv_bfloat16* pEX1w  = symb(d_EX1w);
    __nv_bfloat16* pWSw   = symb(d_WSw);
    float* pBST0 = sym(d_BST0);
    float* pBST1 = sym(d_BST1);
    float* pBSK0 = sym(d_BSK0);
    float* pBEX0 = sym(d_BEX0);
    float* pBEX1 = sym(d_BEX1);

    const int MB = BATCH*NSTMT;  // 640

    init_kernel<<<512, 256>>>();
    build_w<<<(512*H4 + 255)/256, 256>>>(st_Wx, sk_Wx, sk_Wh, ex_Wx, ex_Wh, ws);
    build_b<<<(H4 + 255)/256, 256>>>(st_b, sk_b, ex_b);

    // statement embedder (tensor cores): single LSTM step from zero state
    {
        dim3 g(16, (MB+31)/32);
        gemm_mma_epi<1,8><<<g, 128>>>(node_emb, pST0w, pBST0, nullptr, MB, pTMPH, nullptr, nullptr);
        gemm_mma_epi<1,8><<<g, 128>>>(pTMPH,    pST1w, pBST1, nullptr, MB, pSTMT, nullptr, nullptr);
        gemm_mma_epi<0,8><<<g, 128>>>(pSTMT, pSKX0w, pBSK0, pXG0, MB, nullptr, nullptr, nullptr);
    }

    // skip encoder: 20 independent row-group clusters, 8 CTAs each, local barriers only
    skip_persist<<<NGROUPS*GSZ, 128>>>(ln_s, ln_b);

    // keys = skip @ ws + bs  (big parallel GEMM -> tensor cores)
    {
        int M = BATCH*NNODE*NNODE;
        dim3 g(HID/64, (M+63)/64);
        gemm_mma0<<<g, 128>>>(pSKIP, pWSw, bs, pKEYS, M, HID, HID);
    }

    // main interpreter loop (Q GEMM K-split x4 fp32; exec GEMMs on tensor cores)
    {
        dim3 ge(16, (CHAINS+31)/32);
        for (int step = 0; step < NSTEP; step++) {
            gemm_qk<<<dim3(HID/64, (CHAINS+31)/32, 4), 128>>>(wk);
            attn_kernel<<<CHAINS, 256>>>(bk, w1, b1, step);
            props_kernel<<<CHAINS, 256>>>();
            gemm_mma_epi<4,16><<<ge, 128>>>(pXHE, pEX0w, pBEX0, nullptr, CHAINS, pCPR, pHC, pXH2);
            gemm_mma_epi<5,16><<<ge, 128>>>(pXH2, pEX1w, pBEX1, nullptr, CHAINS, pCPR, pHC, nullptr);
        }
    }

    out_kernel<<<(VOCAB + 255)/256, 256>>>(exit_idx, wo, bo, out);
}

// round 14
// speedup vs baseline: 1.3499x; 1.3499x over previous
#include <cuda_runtime.h>
#include <cuda_bf16.h>
#include <math.h>

// Problem constants
#define BATCH 8
#define NSTMT 80
#define NNODE 81
#define HID   256
#define H4    1024
#define NSTEP 8
#define VOCAB 30000
#define CHAINS (NNODE*BATCH)   // 648
#define NGROUPS 20             // active 32-row groups (rows 640..647 never active)
#define GSZ 16                 // CTAs per row-group: one per column tile

#define ASTR 40   // mma smem A row stride (bf16)
#define BSTR 72   // mma smem B row stride

// ---------------- device scratch (allocation-free) ----------------
static __device__ float d_SKIP[BATCH*NNODE*NNODE*HID];   // [b][start][pos][h]
static __device__ float d_KEYS[BATCH*NNODE*NNODE*HID];
static __device__ float d_STMT[BATCH*NSTMT*HID];
static __device__ float d_TMPH[BATCH*NSTMT*HID];
static __device__ float d_XG0 [BATCH*NSTMT*H4];          // stmt@skWx0 + skb0 (interleaved)
// ping-pong raw skip-LSTM state
static __device__ float d_RC0[2*CHAINS*HID];
static __device__ float d_RH0[2*CHAINS*HID];
static __device__ float d_RC1[2*CHAINS*HID];
static __device__ float d_RH1[2*CHAINS*HID];
// deterministic per-(row, col-tile) partial sums of raw concat state: (sum, sumsq)
static __device__ float2 d_PSA[2][CHAINS][16];   // from phase A (c0,h0)
static __device__ float2 d_PSB[2][CHAINS][16];   // from phase B (c1,h1)
static __device__ float d_HC [CHAINS*H4];   // exec state: c0,h0,c1,h1
static __device__ float d_QP [4][CHAINS*HID];    // K-split Q partials
static __device__ float d_T  [BATCH*NNODE*NNODE];
static __device__ float d_P  [CHAINS];
static __device__ float d_XHE[CHAINS*512];  // [x_in, h0prop]
static __device__ float d_XH2[CHAINS*512];  // [h0new, h1prop]
static __device__ float d_CPR[CHAINS*512];  // [c0prop, c1prop]
// bf16 hi/lo split weights (hi at [0], lo at [K*N]); all gate-interleaved where applicable
static __device__ __nv_bfloat16 d_ST0w [2*HID*H4];
static __device__ __nv_bfloat16 d_ST1w [2*HID*H4];
static __device__ __nv_bfloat16 d_SKX0w[2*HID*H4];
static __device__ __nv_bfloat16 d_SKH0w[2*HID*H4];   // skip L0 recurrent
static __device__ __nv_bfloat16 d_SK1w [2*512*H4];   // skip L1 [Wx1;Wh1]
static __device__ __nv_bfloat16 d_EX0w [2*512*H4];   // [exWx0; exWh0]
static __device__ __nv_bfloat16 d_EX1w [2*512*H4];   // [exWx1; exWh1]
static __device__ __nv_bfloat16 d_WSw  [2*HID*HID];  // keys
static __device__ float d_BST0[H4], d_BST1[H4], d_BSK0[H4], d_BSK1[H4], d_BEX0[H4], d_BEX1[H4];
// per-row-group barrier state (own cache line per group)
static __device__ unsigned g_gcnt[NGROUPS*32];
static __device__ unsigned g_ggen[NGROUPS*32];

// ---------------- helpers ----------------
// Guaranteed fast-math paths (MUFU-based) regardless of compiler flags.
__device__ __forceinline__ float sigf(float x){
    return __fdividef(1.f, 1.f + __expf(-x));
}
__device__ __forceinline__ float ftanh(float x){
    return 1.f - __fdividef(2.f, __expf(2.f*x) + 1.f);
}

// 16-CTA row-group barrier; all CTAs of a group are co-resident
// (ensured by __launch_bounds__(128,3): 456 slots >= 320 blocks).
__device__ __forceinline__ void group_barrier(int grp) {
    __syncthreads();
    if (threadIdx.x == 0) {
        unsigned gen = *(volatile unsigned*)&g_ggen[grp*32];
        __threadfence();
        if (atomicAdd(&g_gcnt[grp*32], 1u) == (unsigned)(GSZ - 1)) {
            atomicExch(&g_gcnt[grp*32], 0u);
            __threadfence();
            atomicExch(&g_ggen[grp*32], gen + 1u);
        } else {
            while (*(volatile unsigned*)&g_ggen[grp*32] == gen) { __nanosleep(32); }
        }
        __threadfence();
    }
    __syncthreads();
}

__device__ __forceinline__ void store_hl(__nv_bfloat16* base, int total, int i, float v) {
    __nv_bfloat16 h = __float2bfloat16(v);
    base[i] = h;
    base[total + i] = __float2bfloat16(v - __bfloat162float(h));
}
__device__ __forceinline__ unsigned pack_hl(float x0, float x1, unsigned& lo_out) {
    __nv_bfloat16 h0 = __float2bfloat16(x0);
    __nv_bfloat16 h1 = __float2bfloat16(x1);
    __nv_bfloat16 l0 = __float2bfloat16(x0 - __bfloat162float(h0));
    __nv_bfloat16 l1 = __float2bfloat16(x1 - __bfloat162float(h1));
    unsigned uh = (unsigned)__bfloat16_as_ushort(h0) | ((unsigned)__bfloat16_as_ushort(h1) << 16);
    lo_out      = (unsigned)__bfloat16_as_ushort(l0) | ((unsigned)__bfloat16_as_ushort(l1) << 16);
    return uh;
}
__device__ __forceinline__ void ldsm_x4(unsigned* r, const __nv_bfloat16* p) {
    unsigned addr = (unsigned)__cvta_generic_to_shared(p);
    asm volatile("ldmatrix.sync.aligned.m8n8.x4.shared.b16 {%0,%1,%2,%3}, [%4];"
        : "=r"(r[0]), "=r"(r[1]), "=r"(r[2]), "=r"(r[3]) : "r"(addr));
}
__device__ __forceinline__ void ldsm_x4_t(unsigned* r, const __nv_bfloat16* p) {
    unsigned addr = (unsigned)__cvta_generic_to_shared(p);
    asm volatile("ldmatrix.sync.aligned.m8n8.x4.trans.shared.b16 {%0,%1,%2,%3}, [%4];"
        : "=r"(r[0]), "=r"(r[1]), "=r"(r[2]), "=r"(r[3]) : "r"(addr));
}
__device__ __forceinline__ void mma_bf16(float* c, const unsigned* a, const unsigned* b) {
    asm volatile("mma.sync.aligned.m16n8k16.row.col.f32.bf16.bf16.f32 "
        "{%0,%1,%2,%3}, {%4,%5,%6,%7}, {%8,%9}, {%0,%1,%2,%3};"
        : "+f"(c[0]), "+f"(c[1]), "+f"(c[2]), "+f"(c[3])
        : "r"(a[0]), "r"(a[1]), "r"(a[2]), "r"(a[3]), "r"(b[0]), "r"(b[1]));
}

// ---------------- init / weight prep ----------------
__global__ void init_kernel() {
    int stride = gridDim.x * blockDim.x;
    int gid = blockIdx.x * blockDim.x + threadIdx.x;
    // d_SKIP's never-written region stays 0 from module init (validated R7..R13).
    for (int i = gid; i < CHAINS*H4; i += stride) d_HC[i] = 0.f;
    for (int i = gid; i < CHAINS; i += stride) d_P[i] = (i % NNODE == 0) ? 1.f : 0.f;
    if (gid < NGROUPS*32) { g_gcnt[gid] = 0u; g_ggen[gid] = 0u; }
}

__global__ void build_w(const float* __restrict__ stWx, const float* __restrict__ skWx,
                        const float* __restrict__ skWh, const float* __restrict__ exWx,
                        const float* __restrict__ exWh, const float* __restrict__ ws) {
    int i = blockIdx.x*256 + threadIdx.x;
    if (i >= 512*H4) return;
    int k = i >> 10, n = i & 1023;
    int h = n >> 2, g = n & 3;
    int sc = h + 256*g;                 // source (non-interleaved) column
    const int L1 = 256*H4;
    float v;
    v = (k < 256) ? skWx[L1 + k*H4 + sc] : skWh[L1 + (k-256)*H4 + sc];
    store_hl(d_SK1w, 512*H4, i, v);
    v = (k < 256) ? exWx[k*H4 + sc]      : exWh[(k-256)*H4 + sc];
    store_hl(d_EX0w, 512*H4, i, v);
    v = (k < 256) ? exWx[L1 + k*H4 + sc] : exWh[L1 + (k-256)*H4 + sc];
    store_hl(d_EX1w, 512*H4, i, v);
    if (k < 256) {
        int j = k*H4 + n;
        store_hl(d_ST0w,  HID*H4, j, stWx[k*H4 + sc]);
        store_hl(d_ST1w,  HID*H4, j, stWx[L1 + k*H4 + sc]);
        store_hl(d_SKX0w, HID*H4, j, skWx[k*H4 + sc]);
        store_hl(d_SKH0w, HID*H4, j, skWh[k*H4 + sc]);
    }
    if (i < HID*HID) store_hl(d_WSw, HID*HID, i, ws[i]);
}

__global__ void build_b(const float* __restrict__ st_b, const float* __restrict__ sk_b,
                        const float* __restrict__ ex_b) {
    int i = blockIdx.x*256 + threadIdx.x;
    if (i >= H4) return;
    int h = i >> 2, g = i & 3;
    int sc = h + 256*g;
    d_BST0[i] = st_b[sc];       d_BST1[i] = st_b[H4 + sc];
    d_BSK0[i] = sk_b[sc];       d_BSK1[i] = sk_b[H4 + sc];
    d_BEX0[i] = ex_b[sc];       d_BEX1[i] = ex_b[H4 + sc];
}

// ---------------- launch-path tensor-core GEMM + fused LSTM epilogues ----------------
// C/out = A[M x (NC*32)] @ B[(NC*32) x 1024] (+interleaved bias).
// 32x64 tile, 128 threads, bf16 hi/lo 3-pass. Fragment layout identical to skip_tile.
// EPI: 0 plain store(+bias), 1 stmt zero-carry cell, 4 exec L0, 5 exec L1
template<int EPI, int NC>
__global__ void __launch_bounds__(128) gemm_mma_epi(
    const float* __restrict__ A, const __nv_bfloat16* __restrict__ Bh_g,
    const float* __restrict__ bias, float* __restrict__ C,
    int M, float* __restrict__ p1, float* __restrict__ p2, float* __restrict__ p3)
{
    const int K = NC << 5;
    const __nv_bfloat16* Bl_g = Bh_g + (size_t)K*H4;
    __shared__ __align__(16) __nv_bfloat16 sAh[2][32*ASTR];
    __shared__ __align__(16) __nv_bfloat16 sAl[2][32*ASTR];
    __shared__ __align__(16) __nv_bfloat16 sBh[2][32*BSTR];
    __shared__ __align__(16) __nv_bfloat16 sBl[2][32*BSTR];
    const int tid = threadIdx.x;
    const int lane = tid & 31, wid = tid >> 5;
    const int wr = wid >> 1, wc = wid & 1;
    const int row0 = blockIdx.y << 5;
    const int col0 = blockIdx.x << 6;
    const int arow = tid >> 2, acol = (tid & 3) << 3;
    const int brow = tid >> 2, bcol = (tid & 3) << 4;
    const int gA = row0 + arow;
    const bool av = gA < M;
    const float* Arow = A + (size_t)gA*K;

    float4 ra0, ra1;
    uint4 wh0, wh1, wl0, wl1;

    #define LOADC(c) do {                                                         \
        int k0_ = (c) << 5;                                                       \
        if (av) {                                                                 \
            ra0 = *(const float4*)(Arow + k0_ + acol);                            \
            ra1 = *(const float4*)(Arow + k0_ + acol + 4);                        \
        } else { ra0 = make_float4(0.f,0.f,0.f,0.f); ra1 = ra0; }                 \
        size_t off_ = (size_t)(k0_ + brow)*H4 + col0 + bcol;                      \
        wh0 = *(const uint4*)(Bh_g + off_); wh1 = *(const uint4*)(Bh_g + off_ + 8); \
        wl0 = *(const uint4*)(Bl_g + off_); wl1 = *(const uint4*)(Bl_g + off_ + 8); \
    } while(0)

    #define STOREC(buf) do {                                                      \
        float v_[8] = {ra0.x, ra0.y, ra0.z, ra0.w, ra1.x, ra1.y, ra1.z, ra1.w};   \
        _Pragma("unroll")                                                         \
        for (int e_ = 0; e_ < 4; e_++) {                                          \
            unsigned ul_;                                                         \
            unsigned uh_ = pack_hl(v_[2*e_], v_[2*e_+1], ul_);                    \
            *reinterpret_cast<unsigned*>(&sAh[buf][arow*ASTR + acol + 2*e_]) = uh_; \
            *reinterpret_cast<unsigned*>(&sAl[buf][arow*ASTR + acol + 2*e_]) = ul_; \
        }                                                                         \
        *(uint4*)&sBh[buf][brow*BSTR + bcol] = wh0;                               \
        *(uint4*)&sBh[buf][brow*BSTR + bcol + 8] = wh1;                           \
        *(uint4*)&sBl[buf][brow*BSTR + bcol] = wl0;                               \
        *(uint4*)&sBl[buf][brow*BSTR + bcol + 8] = wl1;                           \
    } while(0)

    float acc[4][4];
    #pragma unroll
    for (int a = 0; a < 4; a++)
        #pragma unroll
        for (int b = 0; b < 4; b++) acc[a][b] = 0.f;

    LOADC(0); STOREC(0);
    __syncthreads();
    for (int c = 0; c < NC; c++) {
        const int p = c & 1;
        if (c + 1 < NC) LOADC(c + 1);
        #pragma unroll
        for (int kk = 0; kk < 2; kk++) {
            unsigned ah[4], al[4], bh[2][4], bl[2][4];
            const int kc = (kk << 4) + ((lane >> 4) << 3);
            const int r_ = wr*16 + (lane & 15);
            ldsm_x4(ah, &sAh[p][r_*ASTR + kc]);
            ldsm_x4(al, &sAl[p][r_*ASTR + kc]);
            const int kr = (kk << 4) + (lane & 15);
            #pragma unroll
            for (int g2 = 0; g2 < 2; g2++) {
                int nc_ = wc*32 + g2*16 + ((lane >> 4) << 3);
                ldsm_x4_t(bh[g2], &sBh[p][kr*BSTR + nc_]);
                ldsm_x4_t(bl[g2], &sBl[p][kr*BSTR + nc_]);
            }
            #pragma unroll
            for (int nf = 0; nf < 4; nf++) {
                const unsigned* pbh = &bh[nf>>1][(nf&1)<<1];
                const unsigned* pbl = &bl[nf>>1][(nf&1)<<1];
                mma_bf16(acc[nf], ah, pbh);
                mma_bf16(acc[nf], al, pbh);
                mma_bf16(acc[nf], ah, pbl);
            }
        }
        if (c + 1 < NC) {
            STOREC(p ^ 1);
            __syncthreads();
        }
    }
    #undef LOADC
    #undef STOREC

    const int gm0 = row0 + wr*16 + (lane >> 2);
    if (EPI == 0) {
        #pragma unroll
        for (int nf = 0; nf < 4; nf++) {
            int colb = col0 + wc*32 + nf*8 + ((lane & 3) << 1);
            float b0 = bias[colb], b1 = bias[colb+1];
            if (gm0 < M)
                *(float2*)&C[(size_t)gm0*H4 + colb] =
                    make_float2(acc[nf][0]+b0, acc[nf][1]+b1);
            if (gm0+8 < M)
                *(float2*)&C[(size_t)(gm0+8)*H4 + colb] =
                    make_float2(acc[nf][2]+b0, acc[nf][3]+b1);
        }
    } else {
        #pragma unroll
        for (int nf = 0; nf < 4; nf++) {
            float v0 = acc[nf][0], v1 = acc[nf][1], v2 = acc[nf][2], v3 = acc[nf][3];
            float s0 = __shfl_xor_sync(0xffffffffu, v0, 1);
            float s1 = __shfl_xor_sync(0xffffffffu, v1, 1);
            float s2 = __shfl_xor_sync(0xffffffffu, v2, 1);
            float s3 = __shfl_xor_sync(0xffffffffu, v3, 1);
            if (!(lane & 1)) {
                int colb = col0 + wc*32 + nf*8 + ((lane & 3) << 1);
                int u = colb >> 2;
                float4 bv = *(const float4*)&bias[u<<2];
                #pragma unroll
                for (int rr = 0; rr < 2; rr++) {
                    int gm = gm0 + rr*8;
                    if (gm >= M) continue;
                    float gi = (rr ? v2 : v0) + bv.x;
                    float gf = (rr ? v3 : v1) + bv.y;
                    float gg = (rr ? s2 : s0) + bv.z;
                    float go = (rr ? s3 : s1) + bv.w;
                    if (EPI == 1) {
                        float cv = sigf(gi)*ftanh(gg);
                        p1[gm*HID + u] = sigf(go)*ftanh(cv);
                    } else if (EPI == 4) {
                        float cp = p1[gm*512 + u];    // c0 prop
                        float cv = sigf(gf)*cp + sigf(gi)*ftanh(gg);
                        float hv = sigf(go)*ftanh(cv);
                        p2[(size_t)gm*H4 + u]       = cv;
                        p2[(size_t)gm*H4 + HID + u] = hv;
                        p3[gm*512 + u]              = hv;
                    } else {
                        float cp = p1[gm*512 + HID + u];  // c1 prop
                        float cv = sigf(gf)*cp + sigf(gi)*ftanh(gg);
                        float hv = sigf(go)*ftanh(cv);
                        p2[(size_t)gm*H4 + 512 + u] = cv;
                        p2[(size_t)gm*H4 + 768 + u] = hv;
                    }
                }
            }
        }
    }
}

// ---------------- K-split Q GEMM (fp32; unchanged) ----------------
__global__ void __launch_bounds__(128) gemm_qk(const float* __restrict__ wk) {
    __shared__ float As[2][16][36];
    __shared__ float Bs[2][16][64];
    const int tid = threadIdx.x;
    const int tx = tid & 15, ty = tid >> 4;
    const int row0 = blockIdx.y * 32;
    const int col0 = blockIdx.x * 64;
    const int ks = blockIdx.z;
    const int kofs = ks << 8;
    const int am = tid >> 2;
    const int ak = (tid & 3) << 2;
    const int bk = tid >> 4;
    const int bn = (tid & 15) << 2;
    const int gmA = row0 + am;
    const bool av = gmA < CHAINS;
    float acc[4][4] = {};
    float4 ra, rb0, rb1;
    ra = av ? *(const float4*)&d_HC[(size_t)gmA*H4 + kofs + ak] : make_float4(0.f,0.f,0.f,0.f);
    rb0 = *(const float4*)&wk[(size_t)(kofs+bk)*HID + col0 + bn];
    rb1 = *(const float4*)&wk[(size_t)(kofs+bk+8)*HID + col0 + bn];
    As[0][ak][am]=ra.x; As[0][ak+1][am]=ra.y; As[0][ak+2][am]=ra.z; As[0][ak+3][am]=ra.w;
    *(float4*)&Bs[0][bk][bn] = rb0;
    *(float4*)&Bs[0][bk+8][bn] = rb1;
    __syncthreads();
    for (int t = 0; t < 16; t++) {
        const int p = t & 1;
        if (t+1 < 16) {
            int k0 = (t+1) << 4;
            ra = av ? *(const float4*)&d_HC[(size_t)gmA*H4 + kofs + k0 + ak] : make_float4(0.f,0.f,0.f,0.f);
            rb0 = *(const float4*)&wk[(size_t)(kofs+k0+bk)*HID + col0 + bn];
            rb1 = *(const float4*)&wk[(size_t)(kofs+k0+bk+8)*HID + col0 + bn];
        }
        #pragma unroll
        for (int kk = 0; kk < 16; kk++) {
            float4 b4 = *(const float4*)&Bs[p][kk][tx<<2];
            float4 a4 = *(const float4*)&As[p][kk][ty<<2];
            acc[0][0]+=a4.x*b4.x; acc[0][1]+=a4.x*b4.y; acc[0][2]+=a4.x*b4.z; acc[0][3]+=a4.x*b4.w;
            acc[1][0]+=a4.y*b4.x; acc[1][1]+=a4.y*b4.y; acc[1][2]+=a4.y*b4.z; acc[1][3]+=a4.y*b4.w;
            acc[2][0]+=a4.z*b4.x; acc[2][1]+=a4.z*b4.y; acc[2][2]+=a4.z*b4.z; acc[2][3]+=a4.z*b4.w;
            acc[3][0]+=a4.w*b4.x; acc[3][1]+=a4.w*b4.y; acc[3][2]+=a4.w*b4.z; acc[3][3]+=a4.w*b4.w;
        }
        if (t+1 < 16) {
            const int q = p ^ 1;
            As[q][ak][am]=ra.x; As[q][ak+1][am]=ra.y; As[q][ak+2][am]=ra.z; As[q][ak+3][am]=ra.w;
            *(float4*)&Bs[q][bk][bn] = rb0;
            *(float4*)&Bs[q][bk+8][bn] = rb1;
            __syncthreads();
        }
    }
    #pragma unroll
    for (int i = 0; i < 4; i++) {
        int gm = row0 + (ty<<2) + i;
        if (gm >= CHAINS) continue;
        *(float4*)&d_QP[ks][(size_t)gm*HID + col0 + (tx<<2)] =
            make_float4(acc[i][0], acc[i][1], acc[i][2], acc[i][3]);
    }
}

// ---------------- persistent skip encoder (row-group clusters, 16 CTAs/group) -------
struct PSmem {
    __nv_bfloat16 Ah[2][32*ASTR];
    __nv_bfloat16 Al[2][32*ASTR];
    __nv_bfloat16 Bh[2][32*BSTR];
    __nv_bfloat16 Bl[2][32*BSTR];
    float lns[1024], lnb[1024];
    float mu[32], rs[32];
    float2 ps[32][2];
};

template<int PHASE>
__device__ __forceinline__ void skip_tile(
    PSmem& sm, int t, int idx, int actlim, int M, int prv, int cur,
    const float* __restrict__ rh_prev,
    const float* __restrict__ rc_prev,
    const float* __restrict__ rh0_cur,
    float* __restrict__ rc_out, float* __restrict__ rh_out,
    const __nv_bfloat16* __restrict__ WBh, const __nv_bfloat16* __restrict__ WBl)
{
    const int tid = threadIdx.x;
    const int lane = tid & 31, wid = tid >> 5;
    const int wr = wid >> 1, wc = wid & 1;
    const int rt = t >> 4, ct = t & 15;
    const int row0 = rt << 5, col0 = ct << 6;

    const int NC = (PHASE == 0) ? 8 : 16;
    const int arow = tid >> 2, acol = (tid & 3) << 3;
    const int brow = tid >> 2, bcol = (tid & 3) << 4;
    const int gA = row0 + arow;

    float4 rA0_0, rA1_0, rA0_1, rA1_1;
    uint4 rwh0_0, rwh1_0, rwl0_0, rwl1_0;
    uint4 rwh0_1, rwh1_1, rwl0_1, rwl1_1;
    bool act_0 = false, lnf_0 = false, act_1 = false, lnf_1 = false;
    int kb_0 = 0, kb_1 = 0;

    #define LOAD_AB(c, S) do {                                                    \
        int k0_ = (c) << 5;                                                       \
        const float* src_; bool a_; bool l_; int kk0_;                            \
        if (PHASE == 0) { src_ = rh_prev; a_ = (gA < actlim); l_ = true; kk0_ = k0_; } \
        else if (k0_ < 256) { src_ = rh0_cur; a_ = (gA < M); l_ = false; kk0_ = k0_; } \
        else { src_ = rh_prev; a_ = (gA < actlim); l_ = true; kk0_ = k0_ - 256; } \
        act_##S = a_; lnf_##S = l_; kb_##S = kk0_ + acol;                         \
        if (a_) {                                                                 \
            rA0_##S = __ldcg((const float4*)(src_ + (size_t)gA*HID + kk0_ + acol));     \
            rA1_##S = __ldcg((const float4*)(src_ + (size_t)gA*HID + kk0_ + acol + 4)); \
        } else { rA0_##S = make_float4(0.f,0.f,0.f,0.f); rA1_##S = rA0_##S; }     \
        size_t off_ = (size_t)(k0_ + brow)*H4 + col0 + bcol;                      \
        rwh0_##S = *(const uint4*)(WBh + off_); rwh1_##S = *(const uint4*)(WBh + off_ + 8); \
        rwl0_##S = *(const uint4*)(WBl + off_); rwl1_##S = *(const uint4*)(WBl + off_ + 8); \
    } while(0)

    #define STORE_AB(S, BUF) do {                                                 \
        float v_[8] = {rA0_##S.x, rA0_##S.y, rA0_##S.z, rA0_##S.w,                \
                       rA1_##S.x, rA1_##S.y, rA1_##S.z, rA1_##S.w};               \
        if (act_##S && lnf_##S) {                                                 \
            const int lo_ = (PHASE == 0) ? 256 : 768;                             \
            _Pragma("unroll")                                                     \
            for (int e_ = 0; e_ < 8; e_++)                                        \
                v_[e_] = (v_[e_] - muA)*rsA*sm.lns[lo_ + kb_##S + e_] + sm.lnb[lo_ + kb_##S + e_]; \
        }                                                                         \
        _Pragma("unroll")                                                         \
        for (int e_ = 0; e_ < 4; e_++) {                                          \
            unsigned ul_;                                                         \
            unsigned uh_ = pack_hl(v_[2*e_], v_[2*e_+1], ul_);                    \
            *reinterpret_cast<unsigned*>(&sm.Ah[BUF][arow*ASTR + acol + 2*e_]) = uh_; \
            *reinterpret_cast<unsigned*>(&sm.Al[BUF][arow*ASTR + acol + 2*e_]) = ul_; \
        }                                                                         \
        *(uint4*)&sm.Bh[BUF][brow*BSTR + bcol] = rwh0_##S;                        \
        *(uint4*)&sm.Bh[BUF][brow*BSTR + bcol + 8] = rwh1_##S;                    \
        *(uint4*)&sm.Bl[BUF][brow*BSTR + bcol] = rwl0_##S;                        \
        *(uint4*)&sm.Bl[BUF][brow*BSTR + bcol + 8] = rwl1_##S;                    \
    } while(0)

    #define COMPUTE(BUF) do {                                                     \
        _Pragma("unroll")                                                         \
        for (int kk = 0; kk < 2; kk++) {                                          \
            unsigned ah[4], al[4], bh[2][4], bl[2][4];                            \
            const int kc = (kk << 4) + ((lane >> 4) << 3);                        \
            const int r_ = wr*16 + (lane & 15);                                   \
            ldsm_x4(ah, &sm.Ah[BUF][r_*ASTR + kc]);                               \
            ldsm_x4(al, &sm.Al[BUF][r_*ASTR + kc]);                               \
            const int kr = (kk << 4) + (lane & 15);                               \
            _Pragma("unroll")                                                     \
            for (int g2 = 0; g2 < 2; g2++) {                                      \
                int nc_ = wc*32 + g2*16 + ((lane >> 4) << 3);                     \
                ldsm_x4_t(bh[g2], &sm.Bh[BUF][kr*BSTR + nc_]);                    \
                ldsm_x4_t(bl[g2], &sm.Bl[BUF][kr*BSTR + nc_]);                    \
            }                                                                     \
            _Pragma("unroll")                                                     \
            for (int nf = 0; nf < 4; nf++) {                                      \
                const unsigned* pbh = &bh[nf>>1][(nf&1)<<1];                      \
                const unsigned* pbl = &bl[nf>>1][(nf&1)<<1];                      \
                mma_bf16(acc[nf], ah, pbh);                                       \
                mma_bf16(acc[nf], al, pbh);                                       \
                mma_bf16(acc[nf], ah, pbl);                                       \
            }                                                                     \
        }                                                                         \
    } while(0)

    LOAD_AB(0, 0);

    float cpr[2][4];
    const int gm0 = row0 + wr*16 + (lane >> 2);
    #pragma unroll
    for (int rr = 0; rr < 2; rr++)
        #pragma unroll
        for (int nf = 0; nf < 4; nf++) {
            int colb = col0 + wc*32 + nf*8 + ((lane & 3) << 1);
            int u = colb >> 2;
            int gm = gm0 + rr*8;
            cpr[rr][nf] = (gm < actlim) ? __ldcg(rc_prev + (size_t)gm*HID + u) : 0.f;
        }

    {
        int rr = tid >> 2, q = tid & 3;
        int gm = row0 + rr;
        float s = 0.f, s2 = 0.f;
        if (gm < actlim) {
            #pragma unroll
            for (int e = 0; e < 8; e++) {
                int slot = q*8 + e;
                float2 v = (slot < 16) ? __ldcg(&d_PSA[prv][gm][slot])
                                       : __ldcg(&d_PSB[prv][gm][slot-16]);
                s += v.x; s2 += v.y;
            }
        }
        s  += __shfl_xor_sync(0xffffffffu, s, 1);
        s  += __shfl_xor_sync(0xffffffffu, s, 2);
        s2 += __shfl_xor_sync(0xffffffffu, s2, 1);
        s2 += __shfl_xor_sync(0xffffffffu, s2, 2);
        if (q == 0) {
            float mu = s * (1.f/1024.f);
            float var = fmaxf(s2 * (1.f/1024.f) - mu*mu, 0.f);
            sm.mu[rr] = mu;
            sm.rs[rr] = rsqrtf(var + 1e-6f);
        }
    }
    __syncthreads();
    const float muA = sm.mu[arow], rsA = sm.rs[arow];

    float acc[4][4];
    #pragma unroll
    for (int a = 0; a < 4; a++)
        #pragma unroll
        for (int b = 0; b < 4; b++) acc[a][b] = 0.f;

    STORE_AB(0, 0);
    LOAD_AB(1, 1);
    __syncthreads();
    for (int c = 0; c < NC; c += 2) {
        if (c + 2 < NC) LOAD_AB(c + 2, 0);
        COMPUTE(0);
        STORE_AB(1, 1);
        __syncthreads();
        if (c + 3 < NC) LOAD_AB(c + 3, 1);
        COMPUTE(1);
        if (c + 2 < NC) {
            STORE_AB(0, 0);
            __syncthreads();
        }
    }
    #undef LOAD_AB
    #undef STORE_AB
    #undef COMPUTE

    float pv[2] = {0.f, 0.f}, p2v[2] = {0.f, 0.f};
    #pragma unroll
    for (int nf = 0; nf < 4; nf++) {
        float v0 = acc[nf][0], v1 = acc[nf][1], v2 = acc[nf][2], v3 = acc[nf][3];
        float s0 = __shfl_xor_sync(0xffffffffu, v0, 1);
        float s1 = __shfl_xor_sync(0xffffffffu, v1, 1);
        float s2 = __shfl_xor_sync(0xffffffffu, v2, 1);
        float s3 = __shfl_xor_sync(0xffffffffu, v3, 1);
        if (!(lane & 1)) {
            int colb = col0 + wc*32 + nf*8 + ((lane & 3) << 1);
            int u = colb >> 2;
            #pragma unroll
            for (int rr = 0; rr < 2; rr++) {
                int gm = gm0 + rr*8;
                if (gm < M) {
                    int r = gm - row0;
                    float gi = (rr ? v2 : v0), gf = (rr ? v3 : v1);
                    float gg = (rr ? s2 : s0), go = (rr ? s3 : s1);
                    float cp;
                    if (PHASE == 0) {
                        float4 xv = *(const float4*)&d_XG0[((size_t)(gm & 7)*NSTMT + idx)*H4 + (u<<2)];
                        gi += xv.x; gf += xv.y; gg += xv.z; go += xv.w;
                        cp = (gm < actlim)
                           ? (cpr[rr][nf] - sm.mu[r])*sm.rs[r]*sm.lns[u] + sm.lnb[u] : 0.f;
                    } else {
                        float4 bv = *(const float4*)&d_BSK1[u<<2];
                        gi += bv.x; gf += bv.y; gg += bv.z; go += bv.w;
                        cp = (gm < actlim)
                           ? (cpr[rr][nf] - sm.mu[r])*sm.rs[r]*sm.lns[512+u] + sm.lnb[512+u] : 0.f;
                    }
                    float cv = sigf(gf)*cp + sigf(gi)*ftanh(gg);
                    float hv = sigf(go)*ftanh(cv);
                    rc_out[(size_t)gm*HID + u] = cv;
                    rh_out[(size_t)gm*HID + u] = hv;
                    if (PHASE == 1) {
                        int s = gm >> 3, b = gm & 7;
                        d_SKIP[(((size_t)b*NNODE + s)*NNODE + (idx+1))*HID + u] = hv;
                    }
                    pv[rr]  += cv + hv;
                    p2v[rr] += cv*cv + hv*hv;
                }
            }
        }
    }
    #pragma unroll
    for (int rr = 0; rr < 2; rr++) {
        pv[rr]  += __shfl_xor_sync(0xffffffffu, pv[rr], 2);
        p2v[rr] += __shfl_xor_sync(0xffffffffu, p2v[rr], 2);
        if ((lane & 3) == 0) {
            int rit = wr*16 + (lane >> 2) + rr*8;
            sm.ps[rit][wc] = make_float2(pv[rr], p2v[rr]);
        }
    }
    __syncthreads();
    if (tid < 32) {
        int gm = row0 + tid;
        if (gm < M) {
            float2 a = sm.ps[tid][0], b = sm.ps[tid][1];
            float2 o = make_float2(a.x + b.x, a.y + b.y);
            if (PHASE == 0) d_PSA[cur][gm][ct] = o;
            else            d_PSB[cur][gm][ct] = o;
        }
    }
    __syncthreads();
}

// 20 row-groups x 16 CTAs; each CTA owns exactly ONE column tile of its group.
// __launch_bounds__(128,3): 456 residency slots >= 320 blocks -> all groups'
// CTAs co-resident, 16-way local barriers are deadlock-free; ~2.1 CTA/SM keeps
// 8+ warps/SM of latency hiding (the R13 failure was 1 CTA/SM).
__global__ void __launch_bounds__(128, 3) skip_persist(
    const float* __restrict__ lns, const float* __restrict__ lnb)
{
    __shared__ __align__(16) PSmem sm;
    const int tid = threadIdx.x;
    for (int i = tid; i < 1024; i += 128) { sm.lns[i] = lns[i]; sm.lnb[i] = lnb[i]; }
    __syncthreads();

    const int grp = blockIdx.x >> 4;        // row-group 0..19 (rows grp*32..grp*32+31)
    const int ct  = blockIdx.x & 15;        // this CTA's column tile

    for (int idx = grp << 2; idx < NSTMT; idx++) {
        const int M = (idx + 1) << 3;
        const int actlim = idx << 3;
        const int cur = idx & 1, prv = cur ^ 1;
        const float* rh0p = d_RH0 + prv*CHAINS*HID;
        const float* rc0p = d_RC0 + prv*CHAINS*HID;
        const float* rh1p = d_RH1 + prv*CHAINS*HID;
        const float* rc1p = d_RC1 + prv*CHAINS*HID;
        float* rh0c = d_RH0 + cur*CHAINS*HID;
        float* rc0c = d_RC0 + cur*CHAINS*HID;
        float* rh1c = d_RH1 + cur*CHAINS*HID;
        float* rc1c = d_RC1 + cur*CHAINS*HID;

        skip_tile<0>(sm, (grp << 4) | ct, idx, actlim, M, prv, cur,
                     rh0p, rc0p, nullptr, rc0c, rh0c,
                     d_SKH0w, d_SKH0w + HID*H4);
        group_barrier(grp);
        skip_tile<1>(sm, (grp << 4) | ct, idx, actlim, M, prv, cur,
                     rh1p, rc1p, rh0c, rc1c, rh1c,
                     d_SK1w, d_SK1w + 512*H4);
        group_barrier(grp);
    }
}

// ---------------- tensor-core GEMM for the big keys GEMM (unchanged) ----
__global__ void __launch_bounds__(128) gemm_mma0(
    const float* __restrict__ A, const __nv_bfloat16* __restrict__ Bh_g,
    const float* __restrict__ bias, float* __restrict__ C,
    int M, int K, int N)
{
    const __nv_bfloat16* Bl_g = Bh_g + (size_t)K*N;
    __shared__ __align__(16) __nv_bfloat16 sAh[64*ASTR];
    __shared__ __align__(16) __nv_bfloat16 sAl[64*ASTR];
    __shared__ __align__(16) __nv_bfloat16 sBh[32*BSTR];
    __shared__ __align__(16) __nv_bfloat16 sBl[32*BSTR];

    const int tid  = threadIdx.x;
    const int lane = tid & 31;
    const int wid  = tid >> 5;
    const int wr   = wid >> 1;
    const int wc   = wid & 1;
    const int row0 = blockIdx.y << 6;
    const int col0 = blockIdx.x << 6;

    const int arow = tid >> 1;
    const int akq  = (tid & 1) << 4;
    const bool aval = (row0 + arow) < M;
    const float* Ag = A + (size_t)(row0 + arow)*K + akq;
    const int seg0 = tid << 1;

    float acc[2][4][4];
    #pragma unroll
    for (int a = 0; a < 2; a++)
        #pragma unroll
        for (int b = 0; b < 4; b++)
            #pragma unroll
            for (int cc = 0; cc < 4; cc++) acc[a][b][cc] = 0.f;

    const int NC = K >> 5;
    for (int cidx = 0; cidx < NC; cidx++) {
        const int k0 = cidx << 5;
        float av[16];
        #pragma unroll
        for (int j = 0; j < 4; j++) {
            float4 f = aval ? *(const float4*)(Ag + k0 + 4*j) : make_float4(0.f,0.f,0.f,0.f);
            av[4*j]=f.x; av[4*j+1]=f.y; av[4*j+2]=f.z; av[4*j+3]=f.w;
        }
        uint4 bvh[2], bvl[2];
        #pragma unroll
        for (int s = 0; s < 2; s++) {
            int seg = seg0 + s;
            int krow = seg >> 3, nc = (seg & 7) << 3;
            size_t off = (size_t)(k0 + krow)*N + col0 + nc;
            bvh[s] = *(const uint4*)(Bh_g + off);
            bvl[s] = *(const uint4*)(Bl_g + off);
        }
        __syncthreads();
        #pragma unroll
        for (int e = 0; e < 8; e++) {
            unsigned ul;
            unsigned uh = pack_hl(av[2*e], av[2*e+1], ul);
            *reinterpret_cast<unsigned*>(&sAh[arow*ASTR + akq + 2*e]) = uh;
            *reinterpret_cast<unsigned*>(&sAl[arow*ASTR + akq + 2*e]) = ul;
        }
        #pragma unroll
        for (int s = 0; s < 2; s++) {
            int seg = seg0 + s;
            int krow = seg >> 3, nc = (seg & 7) << 3;
            *reinterpret_cast<uint4*>(&sBh[krow*BSTR + nc]) = bvh[s];
            *reinterpret_cast<uint4*>(&sBl[krow*BSTR + nc]) = bvl[s];
        }
        __syncthreads();
        #pragma unroll
        for (int kk = 0; kk < 2; kk++) {
            unsigned ah[2][4], al[2][4], bh[2][4], bl[2][4];
            const int kc = (kk << 4) + ((lane >> 4) << 3);
            #pragma unroll
            for (int mi = 0; mi < 2; mi++) {
                int r = wr*32 + mi*16 + (lane & 15);
                ldsm_x4(ah[mi], &sAh[r*ASTR + kc]);
                ldsm_x4(al[mi], &sAl[r*ASTR + kc]);
            }
            const int kr = (kk << 4) + (lane & 15);
            #pragma unroll
            for (int g2 = 0; g2 < 2; g2++) {
                int nc = wc*32 + g2*16 + ((lane >> 4) << 3);
                ldsm_x4_t(bh[g2], &sBh[kr*BSTR + nc]);
                ldsm_x4_t(bl[g2], &sBl[kr*BSTR + nc]);
            }
            #pragma unroll
            for (int mi = 0; mi < 2; mi++)
                #pragma unroll
                for (int nf = 0; nf < 4; nf++) {
                    const unsigned* pbh = &bh[nf>>1][(nf&1)<<1];
                    const unsigned* pbl = &bl[nf>>1][(nf&1)<<1];
                    mma_bf16(acc[mi][nf], ah[mi], pbh);
                    mma_bf16(acc[mi][nf], al[mi], pbh);
                    mma_bf16(acc[mi][nf], ah[mi], pbl);
                }
        }
    }

    #pragma unroll
    for (int mi = 0; mi < 2; mi++) {
        int gm0 = row0 + wr*32 + mi*16 + (lane >> 2);
        #pragma unroll
        for (int nf = 0; nf < 4; nf++) {
            int colb = col0 + wc*32 + nf*8 + ((lane & 3) << 1);
            float b0 = bias ? bias[colb] : 0.f;
            float b1 = bias ? bias[colb+1] : 0.f;
            if (gm0 < M) {
                float2 o = make_float2(acc[mi][nf][0]+b0, acc[mi][nf][1]+b1);
                *(float2*)&C[(size_t)gm0*N + colb] = o;
            }
            if (gm0+8 < M) {
                float2 o = make_float2(acc[mi][nf][2]+b0, acc[mi][nf][3]+b1);
                *(float2*)&C[(size_t)(gm0+8)*N + colb] = o;
            }
        }
    }
}

// ---------------- main-loop kernels (launch path; unchanged) ----------------
__global__ void __launch_bounds__(256) attn_kernel(const float* __restrict__ bk,
                                                   const float* __restrict__ w1,
                                                   const float* __restrict__ b1, int step) {
    int bn = blockIdx.x;               // b*81 + n
    int n = bn % NNODE;
    __shared__ float qsh[HID], w1sh[HID], lg[NNODE];
    int tid = threadIdx.x;
    {
        float v = bk[tid];
        #pragma unroll
        for (int ks = 0; ks < 4; ks++) v += d_QP[ks][(size_t)bn*HID + tid];
        qsh[tid] = v;
    }
    w1sh[tid] = w1[tid];
    __syncthreads();
    int w = tid >> 5, lane = tid & 31;
    float b1v = b1[0];
    for (int m = w; m < NNODE; m += 8) {
        bool allowed = (step == 0) ? (m == 1)
                    : ((step == NSTEP-1) ? (m == NNODE-1)
                                         : (m > n || m == NNODE-1));
        float acc = 0.f;
        if (allowed) {
            const float* kr = d_KEYS + ((size_t)bn*NNODE + m)*HID;
            #pragma unroll 4
            for (int h = lane; h < HID; h += 32)
                acc += ftanh(qsh[h] + kr[h]) * w1sh[h];
            #pragma unroll
            for (int o = 16; o; o >>= 1) acc += __shfl_xor_sync(0xffffffffu, acc, o);
        }
        if (lane == 0)
            lg[m] = allowed ? (acc + b1v) : -1e9f;
    }
    __syncthreads();
    if (w == 0) {
        float mx = -1e30f;
        for (int m = lane; m < NNODE; m += 32) mx = fmaxf(mx, lg[m]);
        #pragma unroll
        for (int o = 16; o; o >>= 1) mx = fmaxf(mx, __shfl_xor_sync(0xffffffffu, mx, o));
        float sum = 0.f;
        for (int m = lane; m < NNODE; m += 32) { float e = __expf(lg[m]-mx); lg[m] = e; sum += e; }
        #pragma unroll
        for (int o = 16; o; o >>= 1) sum += __shfl_xor_sync(0xffffffffu, sum, o);
        float scale = __fdividef(d_P[bn], sum);
        for (int m = lane; m < NNODE; m += 32) d_T[bn*NNODE + m] = lg[m]*scale;
    }
}

__global__ void __launch_bounds__(256) props_kernel() {
    int bm = blockIdx.x;
    int b = bm / NNODE, m = bm % NNODE;
    __shared__ float tsh[NNODE];
    int tid = threadIdx.x;
    if (tid < NNODE) tsh[tid] = d_T[(b*NNODE+tid)*NNODE + m];
    __syncthreads();
    float s = 0.f;
    for (int n = 0; n < NNODE; n++) s += tsh[n];
    float inv = __fdividef(1.f, s + 1e-7f);
    float ax=0.f, a0=0.f, a1=0.f, a2=0.f, a3=0.f;
    int nlim = (m == NNODE-1) ? NNODE : m;
    for (int n = 0; n < nlim; n++) {
        float tv = tsh[n];
        if (tv == 0.f) continue;
        const float* sr = d_SKIP + (((size_t)b*NNODE+n)*NNODE + m)*HID;
        const float* hr = d_HC + (size_t)(b*NNODE+n)*H4;
        ax += tv*sr[tid];
        a0 += tv*hr[tid];      a1 += tv*hr[256+tid];
        a2 += tv*hr[512+tid];  a3 += tv*hr[768+tid];
    }
    d_XHE[bm*512 + tid]       = ax*inv;  // x_in
    d_CPR[bm*512 + tid]       = a0*inv;  // c0 prop
    d_XHE[bm*512 + 256 + tid] = a1*inv;  // h0 prop
    d_CPR[bm*512 + 256 + tid] = a2*inv;  // c1 prop
    d_XH2[bm*512 + 256 + tid] = a3*inv;  // h1 prop
    if (tid == 0) d_P[bm] = s;
}

// ---------------- output projection ----------------
__global__ void __launch_bounds__(256) out_kernel(const int* __restrict__ exit_idx,
                                                  const float* __restrict__ wo,
                                                  const float* __restrict__ bo,
                                                  float* __restrict__ out) {
    __shared__ float hex[BATCH][HID];
    int tid = threadIdx.x;
    for (int i = tid; i < BATCH*HID; i += 256) {
        int b = i >> 8, h = i & 255;
        hex[b][h] = d_HC[(size_t)(b*NNODE + exit_idx[b])*H4 + 768 + h];
    }
    __syncthreads();
    int col = blockIdx.x*256 + tid;
    if (col >= VOCAB) return;
    float acc[BATCH];
    #pragma unroll
    for (int b = 0; b < BATCH; b++) acc[b] = 0.f;
    for (int h = 0; h < HID; h++) {
        float wv = wo[(size_t)h*VOCAB + col];
        #pragma unroll
        for (int b = 0; b < BATCH; b++) acc[b] += hex[b][h]*wv;
    }
    float bv = bo[col];
    #pragma unroll
    for (int b = 0; b < BATCH; b++) out[b*VOCAB + col] = acc[b] + bv;
}

// ---------------- host ----------------
static inline float* sym(const void* s) {
    void* p = nullptr;
    cudaGetSymbolAddress(&p, s);
    return (float*)p;
}
static inline __nv_bfloat16* symb(const void* s) {
    void* p = nullptr;
    cudaGetSymbolAddress(&p, s);
    return (__nv_bfloat16*)p;
}

extern "C" void kernel_launch(void* const* d_in, const int* in_sizes, int n_in,
                              void* d_out, int out_size) {
    const float* node_emb = (const float*)d_in[0];
    const int*   exit_idx = (const int*)  d_in[10];
    const float* st_Wx = (const float*)d_in[12];
    const float* st_b  = (const float*)d_in[14];
    const float* sk_Wx = (const float*)d_in[15];
    const float* sk_Wh = (const float*)d_in[16];
    const float* sk_b  = (const float*)d_in[17];
    const float* ln_s  = (const float*)d_in[18];
    const float* ln_b  = (const float*)d_in[19];
    const float* ex_Wx = (const float*)d_in[20];
    const float* ex_Wh = (const float*)d_in[21];
    const float* ex_b  = (const float*)d_in[22];
    const float* wk = (const float*)d_in[23];
    const float* bk = (const float*)d_in[24];
    const float* ws = (const float*)d_in[25];
    const float* bs = (const float*)d_in[26];
    const float* w1 = (const float*)d_in[27];
    const float* b1 = (const float*)d_in[28];
    const float* wo = (const float*)d_in[29];
    const float* bo = (const float*)d_in[30];
    float* out = (float*)d_out;

    float* pSTMT = sym(d_STMT);
    float* pTMPH = sym(d_TMPH);
    float* pXG0  = sym(d_XG0);
    float* pSKIP = sym(d_SKIP);
    float* pKEYS = sym(d_KEYS);
    float* pHC   = sym(d_HC);
    float* pXHE  = sym(d_XHE);
    float* pXH2  = sym(d_XH2);
    float* pCPR  = sym(d_CPR);
    __nv_bfloat16* pST0w  = symb(d_ST0w);
    __nv_bfloat16* pST1w  = symb(d_ST1w);
    __nv_bfloat16* pSKX0w = symb(d_SKX0w);
    __nv_bfloat16* pEX0w  = symb(d_EX0w);
    __nv_bfloat16* pEX1w  = symb(d_EX1w);
    __nv_bfloat16* pWSw   = symb(d_WSw);
    float* pBST0 = sym(d_BST0);
    float* pBST1 = sym(d_BST1);
    float* pBSK0 = sym(d_BSK0);
    float* pBEX0 = sym(d_BEX0);
    float* pBEX1 = sym(d_BEX1);

    const int MB = BATCH*NSTMT;  // 640

    init_kernel<<<512, 256>>>();
    build_w<<<(512*H4 + 255)/256, 256>>>(st_Wx, sk_Wx, sk_Wh, ex_Wx, ex_Wh, ws);
    build_b<<<(H4 + 255)/256, 256>>>(st_b, sk_b, ex_b);

    // statement embedder (tensor cores): single LSTM step from zero state
    {
        dim3 g(16, (MB+31)/32);
        gemm_mma_epi<1,8><<<g, 128>>>(node_emb, pST0w, pBST0, nullptr, MB, pTMPH, nullptr, nullptr);
        gemm_mma_epi<1,8><<<g, 128>>>(pTMPH,    pST1w, pBST1, nullptr, MB, pSTMT, nullptr, nullptr);
        gemm_mma_epi<0,8><<<g, 128>>>(pSTMT, pSKX0w, pBSK0, pXG0, MB, nullptr, nullptr, nullptr);
    }

    // skip encoder: 20 row-group clusters x 16 CTAs (1 tile each), local barriers only
    skip_persist<<<NGROUPS*GSZ, 128>>>(ln_s, ln_b);

    // keys = skip @ ws + bs  (big parallel GEMM -> tensor cores)
    {
        int M = BATCH*NNODE*NNODE;
        dim3 g(HID/64, (M+63)/64);
        gemm_mma0<<<g, 128>>>(pSKIP, pWSw, bs, pKEYS, M, HID, HID);
    }

    // main interpreter loop (Q GEMM K-split x4 fp32; exec GEMMs on tensor cores)
    {
        dim3 ge(16, (CHAINS+31)/32);
        for (int step = 0; step < NSTEP; step++) {
            gemm_qk<<<dim3(HID/64, (CHAINS+31)/32, 4), 128>>>(wk);
            attn_kernel<<<CHAINS, 256>>>(bk, w1, b1, step);
            props_kernel<<<CHAINS, 256>>>();
            gemm_mma_epi<4,16><<<ge, 128>>>(pXHE, pEX0w, pBEX0, nullptr, CHAINS, pCPR, pHC, pXH2);
            gemm_mma_epi<5,16><<<ge, 128>>>(pXH2, pEX1w, pBEX1, nullptr, CHAINS, pCPR, pHC, nullptr);
        }
    }

    out_kernel<<<(VOCAB + 255)/256, 256>>>(exit_idx, wo, bo, out);
}

// round 15
// speedup vs baseline: 1.4791x; 1.0957x over previous
#include <cuda_runtime.h>
#include <cuda_bf16.h>
#include <math.h>

// Problem constants
#define BATCH 8
#define NSTMT 80
#define NNODE 81
#define HID   256
#define H4    1024
#define NSTEP 8
#define VOCAB 30000
#define CHAINS (NNODE*BATCH)   // 648
#define NGROUPS 20             // active 32-row groups (rows 640..647 never active)
#define GSZ 16                 // CTAs per row-group: one per column tile

#define ASTR 40   // mma smem A row stride (bf16)
#define BSTR 72   // mma smem B row stride

// ---------------- device scratch (allocation-free) ----------------
static __device__ float d_SKIP[BATCH*NNODE*NNODE*HID];   // [b][start][pos][h]
static __device__ float d_KEYS[BATCH*NNODE*NNODE*HID];
static __device__ float d_STMT[BATCH*NSTMT*HID];
static __device__ float d_TMPH[BATCH*NSTMT*HID];
static __device__ float d_XG0 [BATCH*NSTMT*H4];          // stmt@skWx0 + skb0 (interleaved)
// ping-pong raw skip-LSTM state
static __device__ float d_RC0[2*CHAINS*HID];
static __device__ float d_RH0[2*CHAINS*HID];
static __device__ float d_RC1[2*CHAINS*HID];
static __device__ float d_RH1[2*CHAINS*HID];
// deterministic per-(row, col-tile) partial sums of raw concat state: (sum, sumsq)
static __device__ float2 d_PSA[2][CHAINS][16];   // from phase A (c0,h0)
static __device__ float2 d_PSB[2][CHAINS][16];   // from phase B (c1,h1)
static __device__ float d_HC [CHAINS*H4];   // exec state: c0,h0,c1,h1
static __device__ float d_QP [4][CHAINS*HID];    // K-split Q partials
static __device__ float d_T  [BATCH*NNODE*NNODE];
static __device__ float d_P  [CHAINS];
static __device__ float d_XHE[CHAINS*512];  // [x_in, h0prop]
static __device__ float d_XH2[CHAINS*512];  // [h0new, h1prop]
static __device__ float d_CPR[CHAINS*512];  // [c0prop, c1prop]
// bf16 hi/lo split weights (hi at [0], lo at [K*N]); all gate-interleaved where applicable
static __device__ __nv_bfloat16 d_ST0w [2*HID*H4];
static __device__ __nv_bfloat16 d_ST1w [2*HID*H4];
static __device__ __nv_bfloat16 d_SKX0w[2*HID*H4];
static __device__ __nv_bfloat16 d_SKH0w[2*HID*H4];   // skip L0 recurrent
static __device__ __nv_bfloat16 d_SK1w [2*512*H4];   // skip L1 [Wx1;Wh1]
static __device__ __nv_bfloat16 d_EX0w [2*512*H4];   // [exWx0; exWh0]
static __device__ __nv_bfloat16 d_EX1w [2*512*H4];   // [exWx1; exWh1]
static __device__ __nv_bfloat16 d_WSw  [2*HID*HID];  // keys
static __device__ float d_BST0[H4], d_BST1[H4], d_BSK0[H4], d_BSK1[H4], d_BEX0[H4], d_BEX1[H4];
// per-row-group barrier state (own cache line per group)
static __device__ unsigned g_gcnt[NGROUPS*32];
static __device__ unsigned g_ggen[NGROUPS*32];

// ---------------- helpers ----------------
// Guaranteed fast-math paths (MUFU-based) regardless of compiler flags.
__device__ __forceinline__ float sigf(float x){
    return __fdividef(1.f, 1.f + __expf(-x));
}
__device__ __forceinline__ float ftanh(float x){
    return 1.f - __fdividef(2.f, __expf(2.f*x) + 1.f);
}

// 16-CTA row-group barrier; all CTAs of a group are co-resident
// (skip_persist __launch_bounds__(256,3): >=3 blocks/SM -> 456 slots >= 320 blocks).
__device__ __forceinline__ void group_barrier(int grp) {
    __syncthreads();
    if (threadIdx.x == 0) {
        unsigned gen = *(volatile unsigned*)&g_ggen[grp*32];
        __threadfence();
        if (atomicAdd(&g_gcnt[grp*32], 1u) == (unsigned)(GSZ - 1)) {
            atomicExch(&g_gcnt[grp*32], 0u);
            __threadfence();
            atomicExch(&g_ggen[grp*32], gen + 1u);
        } else {
            while (*(volatile unsigned*)&g_ggen[grp*32] == gen) { __nanosleep(32); }
        }
        __threadfence();
    }
    __syncthreads();
}

__device__ __forceinline__ void store_hl(__nv_bfloat16* base, int total, int i, float v) {
    __nv_bfloat16 h = __float2bfloat16(v);
    base[i] = h;
    base[total + i] = __float2bfloat16(v - __bfloat162float(h));
}
__device__ __forceinline__ unsigned pack_hl(float x0, float x1, unsigned& lo_out) {
    __nv_bfloat16 h0 = __float2bfloat16(x0);
    __nv_bfloat16 h1 = __float2bfloat16(x1);
    __nv_bfloat16 l0 = __float2bfloat16(x0 - __bfloat162float(h0));
    __nv_bfloat16 l1 = __float2bfloat16(x1 - __bfloat162float(h1));
    unsigned uh = (unsigned)__bfloat16_as_ushort(h0) | ((unsigned)__bfloat16_as_ushort(h1) << 16);
    lo_out      = (unsigned)__bfloat16_as_ushort(l0) | ((unsigned)__bfloat16_as_ushort(l1) << 16);
    return uh;
}
__device__ __forceinline__ void ldsm_x4(unsigned* r, const __nv_bfloat16* p) {
    unsigned addr = (unsigned)__cvta_generic_to_shared(p);
    asm volatile("ldmatrix.sync.aligned.m8n8.x4.shared.b16 {%0,%1,%2,%3}, [%4];"
        : "=r"(r[0]), "=r"(r[1]), "=r"(r[2]), "=r"(r[3]) : "r"(addr));
}
__device__ __forceinline__ void ldsm_x4_t(unsigned* r, const __nv_bfloat16* p) {
    unsigned addr = (unsigned)__cvta_generic_to_shared(p);
    asm volatile("ldmatrix.sync.aligned.m8n8.x4.trans.shared.b16 {%0,%1,%2,%3}, [%4];"
        : "=r"(r[0]), "=r"(r[1]), "=r"(r[2]), "=r"(r[3]) : "r"(addr));
}
__device__ __forceinline__ void mma_bf16(float* c, const unsigned* a, const unsigned* b) {
    asm volatile("mma.sync.aligned.m16n8k16.row.col.f32.bf16.bf16.f32 "
        "{%0,%1,%2,%3}, {%4,%5,%6,%7}, {%8,%9}, {%0,%1,%2,%3};"
        : "+f"(c[0]), "+f"(c[1]), "+f"(c[2]), "+f"(c[3])
        : "r"(a[0]), "r"(a[1]), "r"(a[2]), "r"(a[3]), "r"(b[0]), "r"(b[1]));
}

// ---------------- init / weight prep ----------------
__global__ void init_kernel() {
    int stride = gridDim.x * blockDim.x;
    int gid = blockIdx.x * blockDim.x + threadIdx.x;
    // d_SKIP's never-written region stays 0 from module init (validated R7..R14).
    for (int i = gid; i < CHAINS*H4; i += stride) d_HC[i] = 0.f;
    for (int i = gid; i < CHAINS; i += stride) d_P[i] = (i % NNODE == 0) ? 1.f : 0.f;
    if (gid < NGROUPS*32) { g_gcnt[gid] = 0u; g_ggen[gid] = 0u; }
}

__global__ void build_w(const float* __restrict__ stWx, const float* __restrict__ skWx,
                        const float* __restrict__ skWh, const float* __restrict__ exWx,
                        const float* __restrict__ exWh, const float* __restrict__ ws) {
    int i = blockIdx.x*256 + threadIdx.x;
    if (i >= 512*H4) return;
    int k = i >> 10, n = i & 1023;
    int h = n >> 2, g = n & 3;
    int sc = h + 256*g;                 // source (non-interleaved) column
    const int L1 = 256*H4;
    float v;
    v = (k < 256) ? skWx[L1 + k*H4 + sc] : skWh[L1 + (k-256)*H4 + sc];
    store_hl(d_SK1w, 512*H4, i, v);
    v = (k < 256) ? exWx[k*H4 + sc]      : exWh[(k-256)*H4 + sc];
    store_hl(d_EX0w, 512*H4, i, v);
    v = (k < 256) ? exWx[L1 + k*H4 + sc] : exWh[L1 + (k-256)*H4 + sc];
    store_hl(d_EX1w, 512*H4, i, v);
    if (k < 256) {
        int j = k*H4 + n;
        store_hl(d_ST0w,  HID*H4, j, stWx[k*H4 + sc]);
        store_hl(d_ST1w,  HID*H4, j, stWx[L1 + k*H4 + sc]);
        store_hl(d_SKX0w, HID*H4, j, skWx[k*H4 + sc]);
        store_hl(d_SKH0w, HID*H4, j, skWh[k*H4 + sc]);
    }
    if (i < HID*HID) store_hl(d_WSw, HID*HID, i, ws[i]);
}

__global__ void build_b(const float* __restrict__ st_b, const float* __restrict__ sk_b,
                        const float* __restrict__ ex_b) {
    int i = blockIdx.x*256 + threadIdx.x;
    if (i >= H4) return;
    int h = i >> 2, g = i & 3;
    int sc = h + 256*g;
    d_BST0[i] = st_b[sc];       d_BST1[i] = st_b[H4 + sc];
    d_BSK0[i] = sk_b[sc];       d_BSK1[i] = sk_b[H4 + sc];
    d_BEX0[i] = ex_b[sc];       d_BEX1[i] = ex_b[H4 + sc];
}

// ---------------- launch-path tensor-core GEMM + fused LSTM epilogues ----------------
// (unchanged from R14: 32x64 tile, 128 threads, bf16 hi/lo 3-pass)
template<int EPI, int NC>
__global__ void __launch_bounds__(128) gemm_mma_epi(
    const float* __restrict__ A, const __nv_bfloat16* __restrict__ Bh_g,
    const float* __restrict__ bias, float* __restrict__ C,
    int M, float* __restrict__ p1, float* __restrict__ p2, float* __restrict__ p3)
{
    const int K = NC << 5;
    const __nv_bfloat16* Bl_g = Bh_g + (size_t)K*H4;
    __shared__ __align__(16) __nv_bfloat16 sAh[2][32*ASTR];
    __shared__ __align__(16) __nv_bfloat16 sAl[2][32*ASTR];
    __shared__ __align__(16) __nv_bfloat16 sBh[2][32*BSTR];
    __shared__ __align__(16) __nv_bfloat16 sBl[2][32*BSTR];
    const int tid = threadIdx.x;
    const int lane = tid & 31, wid = tid >> 5;
    const int wr = wid >> 1, wc = wid & 1;
    const int row0 = blockIdx.y << 5;
    const int col0 = blockIdx.x << 6;
    const int arow = tid >> 2, acol = (tid & 3) << 3;
    const int brow = tid >> 2, bcol = (tid & 3) << 4;
    const int gA = row0 + arow;
    const bool av = gA < M;
    const float* Arow = A + (size_t)gA*K;

    float4 ra0, ra1;
    uint4 wh0, wh1, wl0, wl1;

    #define LOADC(c) do {                                                         \
        int k0_ = (c) << 5;                                                       \
        if (av) {                                                                 \
            ra0 = *(const float4*)(Arow + k0_ + acol);                            \
            ra1 = *(const float4*)(Arow + k0_ + acol + 4);                        \
        } else { ra0 = make_float4(0.f,0.f,0.f,0.f); ra1 = ra0; }                 \
        size_t off_ = (size_t)(k0_ + brow)*H4 + col0 + bcol;                      \
        wh0 = *(const uint4*)(Bh_g + off_); wh1 = *(const uint4*)(Bh_g + off_ + 8); \
        wl0 = *(const uint4*)(Bl_g + off_); wl1 = *(const uint4*)(Bl_g + off_ + 8); \
    } while(0)

    #define STOREC(buf) do {                                                      \
        float v_[8] = {ra0.x, ra0.y, ra0.z, ra0.w, ra1.x, ra1.y, ra1.z, ra1.w};   \
        _Pragma("unroll")                                                         \
        for (int e_ = 0; e_ < 4; e_++) {                                          \
            unsigned ul_;                                                         \
            unsigned uh_ = pack_hl(v_[2*e_], v_[2*e_+1], ul_);                    \
            *reinterpret_cast<unsigned*>(&sAh[buf][arow*ASTR + acol + 2*e_]) = uh_; \
            *reinterpret_cast<unsigned*>(&sAl[buf][arow*ASTR + acol + 2*e_]) = ul_; \
        }                                                                         \
        *(uint4*)&sBh[buf][brow*BSTR + bcol] = wh0;                               \
        *(uint4*)&sBh[buf][brow*BSTR + bcol + 8] = wh1;                           \
        *(uint4*)&sBl[buf][brow*BSTR + bcol] = wl0;                               \
        *(uint4*)&sBl[buf][brow*BSTR + bcol + 8] = wl1;                           \
    } while(0)

    float acc[4][4];
    #pragma unroll
    for (int a = 0; a < 4; a++)
        #pragma unroll
        for (int b = 0; b < 4; b++) acc[a][b] = 0.f;

    LOADC(0); STOREC(0);
    __syncthreads();
    for (int c = 0; c < NC; c++) {
        const int p = c & 1;
        if (c + 1 < NC) LOADC(c + 1);
        #pragma unroll
        for (int kk = 0; kk < 2; kk++) {
            unsigned ah[4], al[4], bh[2][4], bl[2][4];
            const int kc = (kk << 4) + ((lane >> 4) << 3);
            const int r_ = wr*16 + (lane & 15);
            ldsm_x4(ah, &sAh[p][r_*ASTR + kc]);
            ldsm_x4(al, &sAl[p][r_*ASTR + kc]);
            const int kr = (kk << 4) + (lane & 15);
            #pragma unroll
            for (int g2 = 0; g2 < 2; g2++) {
                int nc_ = wc*32 + g2*16 + ((lane >> 4) << 3);
                ldsm_x4_t(bh[g2], &sBh[p][kr*BSTR + nc_]);
                ldsm_x4_t(bl[g2], &sBl[p][kr*BSTR + nc_]);
            }
            #pragma unroll
            for (int nf = 0; nf < 4; nf++) {
                const unsigned* pbh = &bh[nf>>1][(nf&1)<<1];
                const unsigned* pbl = &bl[nf>>1][(nf&1)<<1];
                mma_bf16(acc[nf], ah, pbh);
                mma_bf16(acc[nf], al, pbh);
                mma_bf16(acc[nf], ah, pbl);
            }
        }
        if (c + 1 < NC) {
            STOREC(p ^ 1);
            __syncthreads();
        }
    }
    #undef LOADC
    #undef STOREC

    const int gm0 = row0 + wr*16 + (lane >> 2);
    if (EPI == 0) {
        #pragma unroll
        for (int nf = 0; nf < 4; nf++) {
            int colb = col0 + wc*32 + nf*8 + ((lane & 3) << 1);
            float b0 = bias[colb], b1 = bias[colb+1];
            if (gm0 < M)
                *(float2*)&C[(size_t)gm0*H4 + colb] =
                    make_float2(acc[nf][0]+b0, acc[nf][1]+b1);
            if (gm0+8 < M)
                *(float2*)&C[(size_t)(gm0+8)*H4 + colb] =
                    make_float2(acc[nf][2]+b0, acc[nf][3]+b1);
        }
    } else {
        #pragma unroll
        for (int nf = 0; nf < 4; nf++) {
            float v0 = acc[nf][0], v1 = acc[nf][1], v2 = acc[nf][2], v3 = acc[nf][3];
            float s0 = __shfl_xor_sync(0xffffffffu, v0, 1);
            float s1 = __shfl_xor_sync(0xffffffffu, v1, 1);
            float s2 = __shfl_xor_sync(0xffffffffu, v2, 1);
            float s3 = __shfl_xor_sync(0xffffffffu, v3, 1);
            if (!(lane & 1)) {
                int colb = col0 + wc*32 + nf*8 + ((lane & 3) << 1);
                int u = colb >> 2;
                float4 bv = *(const float4*)&bias[u<<2];
                #pragma unroll
                for (int rr = 0; rr < 2; rr++) {
                    int gm = gm0 + rr*8;
                    if (gm >= M) continue;
                    float gi = (rr ? v2 : v0) + bv.x;
                    float gf = (rr ? v3 : v1) + bv.y;
                    float gg = (rr ? s2 : s0) + bv.z;
                    float go = (rr ? s3 : s1) + bv.w;
                    if (EPI == 1) {
                        float cv = sigf(gi)*ftanh(gg);
                        p1[gm*HID + u] = sigf(go)*ftanh(cv);
                    } else if (EPI == 4) {
                        float cp = p1[gm*512 + u];    // c0 prop
                        float cv = sigf(gf)*cp + sigf(gi)*ftanh(gg);
                        float hv = sigf(go)*ftanh(cv);
                        p2[(size_t)gm*H4 + u]       = cv;
                        p2[(size_t)gm*H4 + HID + u] = hv;
                        p3[gm*512 + u]              = hv;
                    } else {
                        float cp = p1[gm*512 + HID + u];  // c1 prop
                        float cv = sigf(gf)*cp + sigf(gi)*ftanh(gg);
                        float hv = sigf(go)*ftanh(cv);
                        p2[(size_t)gm*H4 + 512 + u] = cv;
                        p2[(size_t)gm*H4 + 768 + u] = hv;
                    }
                }
            }
        }
    }
}

// ---------------- K-split Q GEMM (fp32; unchanged) ----------------
__global__ void __launch_bounds__(128) gemm_qk(const float* __restrict__ wk) {
    __shared__ float As[2][16][36];
    __shared__ float Bs[2][16][64];
    const int tid = threadIdx.x;
    const int tx = tid & 15, ty = tid >> 4;
    const int row0 = blockIdx.y * 32;
    const int col0 = blockIdx.x * 64;
    const int ks = blockIdx.z;
    const int kofs = ks << 8;
    const int am = tid >> 2;
    const int ak = (tid & 3) << 2;
    const int bk = tid >> 4;
    const int bn = (tid & 15) << 2;
    const int gmA = row0 + am;
    const bool av = gmA < CHAINS;
    float acc[4][4] = {};
    float4 ra, rb0, rb1;
    ra = av ? *(const float4*)&d_HC[(size_t)gmA*H4 + kofs + ak] : make_float4(0.f,0.f,0.f,0.f);
    rb0 = *(const float4*)&wk[(size_t)(kofs+bk)*HID + col0 + bn];
    rb1 = *(const float4*)&wk[(size_t)(kofs+bk+8)*HID + col0 + bn];
    As[0][ak][am]=ra.x; As[0][ak+1][am]=ra.y; As[0][ak+2][am]=ra.z; As[0][ak+3][am]=ra.w;
    *(float4*)&Bs[0][bk][bn] = rb0;
    *(float4*)&Bs[0][bk+8][bn] = rb1;
    __syncthreads();
    for (int t = 0; t < 16; t++) {
        const int p = t & 1;
        if (t+1 < 16) {
            int k0 = (t+1) << 4;
            ra = av ? *(const float4*)&d_HC[(size_t)gmA*H4 + kofs + k0 + ak] : make_float4(0.f,0.f,0.f,0.f);
            rb0 = *(const float4*)&wk[(size_t)(kofs+k0+bk)*HID + col0 + bn];
            rb1 = *(const float4*)&wk[(size_t)(kofs+k0+bk+8)*HID + col0 + bn];
        }
        #pragma unroll
        for (int kk = 0; kk < 16; kk++) {
            float4 b4 = *(const float4*)&Bs[p][kk][tx<<2];
            float4 a4 = *(const float4*)&As[p][kk][ty<<2];
            acc[0][0]+=a4.x*b4.x; acc[0][1]+=a4.x*b4.y; acc[0][2]+=a4.x*b4.z; acc[0][3]+=a4.x*b4.w;
            acc[1][0]+=a4.y*b4.x; acc[1][1]+=a4.y*b4.y; acc[1][2]+=a4.y*b4.z; acc[1][3]+=a4.y*b4.w;
            acc[2][0]+=a4.z*b4.x; acc[2][1]+=a4.z*b4.y; acc[2][2]+=a4.z*b4.z; acc[2][3]+=a4.z*b4.w;
            acc[3][0]+=a4.w*b4.x; acc[3][1]+=a4.w*b4.y; acc[3][2]+=a4.w*b4.z; acc[3][3]+=a4.w*b4.w;
        }
        if (t+1 < 16) {
            const int q = p ^ 1;
            As[q][ak][am]=ra.x; As[q][ak+1][am]=ra.y; As[q][ak+2][am]=ra.z; As[q][ak+3][am]=ra.w;
            *(float4*)&Bs[q][bk][bn] = rb0;
            *(float4*)&Bs[q][bk+8][bn] = rb1;
            __syncthreads();
        }
    }
    #pragma unroll
    for (int i = 0; i < 4; i++) {
        int gm = row0 + (ty<<2) + i;
        if (gm >= CHAINS) continue;
        *(float4*)&d_QP[ks][(size_t)gm*HID + col0 + (tx<<2)] =
            make_float4(acc[i][0], acc[i][1], acc[i][2], acc[i][3]);
    }
}

// ---------------- persistent skip encoder: 256-thread tiles (8 warps), clusters -----
struct PSmem {
    __nv_bfloat16 Ah[2][32*ASTR];
    __nv_bfloat16 Al[2][32*ASTR];
    __nv_bfloat16 Bh[2][32*BSTR];
    __nv_bfloat16 Bl[2][32*BSTR];
    float lns[1024], lnb[1024];
    float mu[32], rs[32];
    float2 ps[32][4];
};

// 8-warp tile: warp (wr = wid&1) owns rows [wr*16,+16); (wc = wid>>1) owns cols
// [wc*16,+16) of the 64-wide tile -> 12 mma/chunk/warp (vs 24 at 4 warps).
template<int PHASE>
__device__ __forceinline__ void skip_tile(
    PSmem& sm, int t, int idx, int actlim, int M, int prv, int cur,
    const float* __restrict__ rh_prev,
    const float* __restrict__ rc_prev,
    const float* __restrict__ rh0_cur,
    float* __restrict__ rc_out, float* __restrict__ rh_out,
    const __nv_bfloat16* __restrict__ WBh, const __nv_bfloat16* __restrict__ WBl)
{
    const int tid = threadIdx.x;
    const int lane = tid & 31, wid = tid >> 5;
    const int wr = wid & 1, wc = wid >> 1;       // 2 x 4 warp layout
    const int rt = t >> 4, ct = t & 15;
    const int row0 = rt << 5, col0 = ct << 6;

    const int NC = (PHASE == 0) ? 8 : 16;
    const int arow = tid >> 3, acol = (tid & 7) << 2;   // A: 32r x 32k, 4 f32/thread
    const int brow = tid >> 3, bcol = (tid & 7) << 3;   // B: 32k x 64n, 8 bf16/thread
    const int gA = row0 + arow;

    float4 rA_0, rA_1;
    uint4 rwh_0, rwl_0, rwh_1, rwl_1;
    bool act_0 = false, lnf_0 = false, act_1 = false, lnf_1 = false;
    int kb_0 = 0, kb_1 = 0;

    #define LOAD_AB(c, S) do {                                                    \
        int k0_ = (c) << 5;                                                       \
        const float* src_; bool a_; bool l_; int kk0_;                            \
        if (PHASE == 0) { src_ = rh_prev; a_ = (gA < actlim); l_ = true; kk0_ = k0_; } \
        else if (k0_ < 256) { src_ = rh0_cur; a_ = (gA < M); l_ = false; kk0_ = k0_; } \
        else { src_ = rh_prev; a_ = (gA < actlim); l_ = true; kk0_ = k0_ - 256; } \
        act_##S = a_; lnf_##S = l_; kb_##S = kk0_ + acol;                         \
        if (a_) rA_##S = __ldcg((const float4*)(src_ + (size_t)gA*HID + kk0_ + acol)); \
        else rA_##S = make_float4(0.f,0.f,0.f,0.f);                               \
        size_t off_ = (size_t)(k0_ + brow)*H4 + col0 + bcol;                      \
        rwh_##S = *(const uint4*)(WBh + off_);                                    \
        rwl_##S = *(const uint4*)(WBl + off_);                                    \
    } while(0)

    #define STORE_AB(S, BUF) do {                                                 \
        float v_[4] = {rA_##S.x, rA_##S.y, rA_##S.z, rA_##S.w};                   \
        if (act_##S && lnf_##S) {                                                 \
            const int lo_ = (PHASE == 0) ? 256 : 768;                             \
            _Pragma("unroll")                                                     \
            for (int e_ = 0; e_ < 4; e_++)                                        \
                v_[e_] = (v_[e_] - muA)*rsA*sm.lns[lo_ + kb_##S + e_] + sm.lnb[lo_ + kb_##S + e_]; \
        }                                                                         \
        _Pragma("unroll")                                                         \
        for (int e_ = 0; e_ < 2; e_++) {                                          \
            unsigned ul_;                                                         \
            unsigned uh_ = pack_hl(v_[2*e_], v_[2*e_+1], ul_);                    \
            *reinterpret_cast<unsigned*>(&sm.Ah[BUF][arow*ASTR + acol + 2*e_]) = uh_; \
            *reinterpret_cast<unsigned*>(&sm.Al[BUF][arow*ASTR + acol + 2*e_]) = ul_; \
        }                                                                         \
        *(uint4*)&sm.Bh[BUF][brow*BSTR + bcol] = rwh_##S;                         \
        *(uint4*)&sm.Bl[BUF][brow*BSTR + bcol] = rwl_##S;                         \
    } while(0)

    #define COMPUTE(BUF) do {                                                     \
        _Pragma("unroll")                                                         \
        for (int kk = 0; kk < 2; kk++) {                                          \
            unsigned ah[4], al[4], bh[4], bl[4];                                  \
            const int kc = (kk << 4) + ((lane >> 4) << 3);                        \
            const int r_ = wr*16 + (lane & 15);                                   \
            ldsm_x4(ah, &sm.Ah[BUF][r_*ASTR + kc]);                               \
            ldsm_x4(al, &sm.Al[BUF][r_*ASTR + kc]);                               \
            const int kr = (kk << 4) + (lane & 15);                               \
            const int nc_ = wc*16 + ((lane >> 4) << 3);                           \
            ldsm_x4_t(bh, &sm.Bh[BUF][kr*BSTR + nc_]);                            \
            ldsm_x4_t(bl, &sm.Bl[BUF][kr*BSTR + nc_]);                            \
            _Pragma("unroll")                                                     \
            for (int nf = 0; nf < 2; nf++) {                                      \
                const unsigned* pbh = &bh[nf<<1];                                 \
                const unsigned* pbl = &bl[nf<<1];                                 \
                mma_bf16(acc[nf], ah, pbh);                                       \
                mma_bf16(acc[nf], al, pbh);                                       \
                mma_bf16(acc[nf], ah, pbl);                                       \
            }                                                                     \
        }                                                                         \
    } while(0)

    LOAD_AB(0, 0);

    float cpr[2][2];
    const int gm0 = row0 + wr*16 + (lane >> 2);
    #pragma unroll
    for (int rr = 0; rr < 2; rr++)
        #pragma unroll
        for (int nf = 0; nf < 2; nf++) {
            int colb = col0 + wc*16 + nf*8 + ((lane & 3) << 1);
            int u = colb >> 2;
            int gm = gm0 + rr*8;
            cpr[rr][nf] = (gm < actlim) ? __ldcg(rc_prev + (size_t)gm*HID + u) : 0.f;
        }

    if (tid < 128) {
        int rr = tid >> 2, q = tid & 3;
        int gm = row0 + rr;
        float s = 0.f, s2 = 0.f;
        if (gm < actlim) {
            #pragma unroll
            for (int e = 0; e < 8; e++) {
                int slot = q*8 + e;
                float2 v = (slot < 16) ? __ldcg(&d_PSA[prv][gm][slot])
                                       : __ldcg(&d_PSB[prv][gm][slot-16]);
                s += v.x; s2 += v.y;
            }
        }
        s  += __shfl_xor_sync(0xffffffffu, s, 1);
        s  += __shfl_xor_sync(0xffffffffu, s, 2);
        s2 += __shfl_xor_sync(0xffffffffu, s2, 1);
        s2 += __shfl_xor_sync(0xffffffffu, s2, 2);
        if (q == 0) {
            float mu = s * (1.f/1024.f);
            float var = fmaxf(s2 * (1.f/1024.f) - mu*mu, 0.f);
            sm.mu[rr] = mu;
            sm.rs[rr] = rsqrtf(var + 1e-6f);
        }
    }
    __syncthreads();
    const float muA = sm.mu[arow], rsA = sm.rs[arow];

    float acc[2][4];
    #pragma unroll
    for (int a = 0; a < 2; a++)
        #pragma unroll
        for (int b = 0; b < 4; b++) acc[a][b] = 0.f;

    STORE_AB(0, 0);
    LOAD_AB(1, 1);
    __syncthreads();
    for (int c = 0; c < NC; c += 2) {
        if (c + 2 < NC) LOAD_AB(c + 2, 0);
        COMPUTE(0);
        STORE_AB(1, 1);
        __syncthreads();
        if (c + 3 < NC) LOAD_AB(c + 3, 1);
        COMPUTE(1);
        if (c + 2 < NC) {
            STORE_AB(0, 0);
            __syncthreads();
        }
    }
    #undef LOAD_AB
    #undef STORE_AB
    #undef COMPUTE

    // ---- epilogue: LSTM cell + raw state + partial sums ----
    float pv[2] = {0.f, 0.f}, p2v[2] = {0.f, 0.f};
    #pragma unroll
    for (int nf = 0; nf < 2; nf++) {
        float v0 = acc[nf][0], v1 = acc[nf][1], v2 = acc[nf][2], v3 = acc[nf][3];
        float s0 = __shfl_xor_sync(0xffffffffu, v0, 1);
        float s1 = __shfl_xor_sync(0xffffffffu, v1, 1);
        float s2 = __shfl_xor_sync(0xffffffffu, v2, 1);
        float s3 = __shfl_xor_sync(0xffffffffu, v3, 1);
        if (!(lane & 1)) {
            int colb = col0 + wc*16 + nf*8 + ((lane & 3) << 1);
            int u = colb >> 2;
            #pragma unroll
            for (int rr = 0; rr < 2; rr++) {
                int gm = gm0 + rr*8;
                if (gm < M) {
                    int r = gm - row0;
                    float gi = (rr ? v2 : v0), gf = (rr ? v3 : v1);
                    float gg = (rr ? s2 : s0), go = (rr ? s3 : s1);
                    float cp;
                    if (PHASE == 0) {
                        float4 xv = *(const float4*)&d_XG0[((size_t)(gm & 7)*NSTMT + idx)*H4 + (u<<2)];
                        gi += xv.x; gf += xv.y; gg += xv.z; go += xv.w;
                        cp = (gm < actlim)
                           ? (cpr[rr][nf] - sm.mu[r])*sm.rs[r]*sm.lns[u] + sm.lnb[u] : 0.f;
                    } else {
                        float4 bv = *(const float4*)&d_BSK1[u<<2];
                        gi += bv.x; gf += bv.y; gg += bv.z; go += bv.w;
                        cp = (gm < actlim)
                           ? (cpr[rr][nf] - sm.mu[r])*sm.rs[r]*sm.lns[512+u] + sm.lnb[512+u] : 0.f;
                    }
                    float cv = sigf(gf)*cp + sigf(gi)*ftanh(gg);
                    float hv = sigf(go)*ftanh(cv);
                    rc_out[(size_t)gm*HID + u] = cv;
                    rh_out[(size_t)gm*HID + u] = hv;
                    if (PHASE == 1) {
                        int s = gm >> 3, b = gm & 7;
                        d_SKIP[(((size_t)b*NNODE + s)*NNODE + (idx+1))*HID + u] = hv;
                    }
                    pv[rr]  += cv + hv;
                    p2v[rr] += cv*cv + hv*hv;
                }
            }
        }
    }
    #pragma unroll
    for (int rr = 0; rr < 2; rr++) {
        pv[rr]  += __shfl_xor_sync(0xffffffffu, pv[rr], 2);
        p2v[rr] += __shfl_xor_sync(0xffffffffu, p2v[rr], 2);
        if ((lane & 3) == 0) {
            int rit = wr*16 + (lane >> 2) + rr*8;
            sm.ps[rit][wc] = make_float2(pv[rr], p2v[rr]);
        }
    }
    __syncthreads();
    if (tid < 32) {
        int gm = row0 + tid;
        if (gm < M) {
            float2 a = sm.ps[tid][0], b = sm.ps[tid][1];
            float2 c2 = sm.ps[tid][2], d2 = sm.ps[tid][3];
            float2 o = make_float2(a.x + b.x + c2.x + d2.x, a.y + b.y + c2.y + d2.y);
            if (PHASE == 0) d_PSA[cur][gm][ct] = o;
            else            d_PSB[cur][gm][ct] = o;
        }
    }
    __syncthreads();
}

// 20 row-groups x 16 CTAs (256 thr, 8 warps each); one column tile per CTA.
// __launch_bounds__(256,3): regs<=85 -> >=3 blocks/SM -> 456 slots >= 320 blocks.
__global__ void __launch_bounds__(256, 3) skip_persist(
    const float* __restrict__ lns, const float* __restrict__ lnb)
{
    __shared__ __align__(16) PSmem sm;
    const int tid = threadIdx.x;
    for (int i = tid; i < 1024; i += 256) { sm.lns[i] = lns[i]; sm.lnb[i] = lnb[i]; }
    __syncthreads();

    const int grp = blockIdx.x >> 4;        // row-group 0..19 (rows grp*32..grp*32+31)
    const int ct  = blockIdx.x & 15;        // this CTA's column tile

    for (int idx = grp << 2; idx < NSTMT; idx++) {
        const int M = (idx + 1) << 3;
        const int actlim = idx << 3;
        const int cur = idx & 1, prv = cur ^ 1;
        const float* rh0p = d_RH0 + prv*CHAINS*HID;
        const float* rc0p = d_RC0 + prv*CHAINS*HID;
        const float* rh1p = d_RH1 + prv*CHAINS*HID;
        const float* rc1p = d_RC1 + prv*CHAINS*HID;
        float* rh0c = d_RH0 + cur*CHAINS*HID;
        float* rc0c = d_RC0 + cur*CHAINS*HID;
        float* rh1c = d_RH1 + cur*CHAINS*HID;
        float* rc1c = d_RC1 + cur*CHAINS*HID;

        skip_tile<0>(sm, (grp << 4) | ct, idx, actlim, M, prv, cur,
                     rh0p, rc0p, nullptr, rc0c, rh0c,
                     d_SKH0w, d_SKH0w + HID*H4);
        group_barrier(grp);
        skip_tile<1>(sm, (grp << 4) | ct, idx, actlim, M, prv, cur,
                     rh1p, rc1p, rh0c, rc1c, rh1c,
                     d_SK1w, d_SK1w + 512*H4);
        group_barrier(grp);
    }
}

// ---------------- tensor-core GEMM for the big keys GEMM (unchanged) ----
__global__ void __launch_bounds__(128) gemm_mma0(
    const float* __restrict__ A, const __nv_bfloat16* __restrict__ Bh_g,
    const float* __restrict__ bias, float* __restrict__ C,
    int M, int K, int N)
{
    const __nv_bfloat16* Bl_g = Bh_g + (size_t)K*N;
    __shared__ __align__(16) __nv_bfloat16 sAh[64*ASTR];
    __shared__ __align__(16) __nv_bfloat16 sAl[64*ASTR];
    __shared__ __align__(16) __nv_bfloat16 sBh[32*BSTR];
    __shared__ __align__(16) __nv_bfloat16 sBl[32*BSTR];

    const int tid  = threadIdx.x;
    const int lane = tid & 31;
    const int wid  = tid >> 5;
    const int wr   = wid >> 1;
    const int wc   = wid & 1;
    const int row0 = blockIdx.y << 6;
    const int col0 = blockIdx.x << 6;

    const int arow = tid >> 1;
    const int akq  = (tid & 1) << 4;
    const bool aval = (row0 + arow) < M;
    const float* Ag = A + (size_t)(row0 + arow)*K + akq;
    const int seg0 = tid << 1;

    float acc[2][4][4];
    #pragma unroll
    for (int a = 0; a < 2; a++)
        #pragma unroll
        for (int b = 0; b < 4; b++)
            #pragma unroll
            for (int cc = 0; cc < 4; cc++) acc[a][b][cc] = 0.f;

    const int NC = K >> 5;
    for (int cidx = 0; cidx < NC; cidx++) {
        const int k0 = cidx << 5;
        float av[16];
        #pragma unroll
        for (int j = 0; j < 4; j++) {
            float4 f = aval ? *(const float4*)(Ag + k0 + 4*j) : make_float4(0.f,0.f,0.f,0.f);
            av[4*j]=f.x; av[4*j+1]=f.y; av[4*j+2]=f.z; av[4*j+3]=f.w;
        }
        uint4 bvh[2], bvl[2];
        #pragma unroll
        for (int s = 0; s < 2; s++) {
            int seg = seg0 + s;
            int krow = seg >> 3, nc = (seg & 7) << 3;
            size_t off = (size_t)(k0 + krow)*N + col0 + nc;
            bvh[s] = *(const uint4*)(Bh_g + off);
            bvl[s] = *(const uint4*)(Bl_g + off);
        }
        __syncthreads();
        #pragma unroll
        for (int e = 0; e < 8; e++) {
            unsigned ul;
            unsigned uh = pack_hl(av[2*e], av[2*e+1], ul);
            *reinterpret_cast<unsigned*>(&sAh[arow*ASTR + akq + 2*e]) = uh;
            *reinterpret_cast<unsigned*>(&sAl[arow*ASTR + akq + 2*e]) = ul;
        }
        #pragma unroll
        for (int s = 0; s < 2; s++) {
            int seg = seg0 + s;
            int krow = seg >> 3, nc = (seg & 7) << 3;
            *reinterpret_cast<uint4*>(&sBh[krow*BSTR + nc]) = bvh[s];
            *reinterpret_cast<uint4*>(&sBl[krow*BSTR + nc]) = bvl[s];
        }
        __syncthreads();
        #pragma unroll
        for (int kk = 0; kk < 2; kk++) {
            unsigned ah[2][4], al[2][4], bh[2][4], bl[2][4];
            const int kc = (kk << 4) + ((lane >> 4) << 3);
            #pragma unroll
            for (int mi = 0; mi < 2; mi++) {
                int r = wr*32 + mi*16 + (lane & 15);
                ldsm_x4(ah[mi], &sAh[r*ASTR + kc]);
                ldsm_x4(al[mi], &sAl[r*ASTR + kc]);
            }
            const int kr = (kk << 4) + (lane & 15);
            #pragma unroll
            for (int g2 = 0; g2 < 2; g2++) {
                int nc = wc*32 + g2*16 + ((lane >> 4) << 3);
                ldsm_x4_t(bh[g2], &sBh[kr*BSTR + nc]);
                ldsm_x4_t(bl[g2], &sBl[kr*BSTR + nc]);
            }
            #pragma unroll
            for (int mi = 0; mi < 2; mi++)
                #pragma unroll
                for (int nf = 0; nf < 4; nf++) {
                    const unsigned* pbh = &bh[nf>>1][(nf&1)<<1];
                    const unsigned* pbl = &bl[nf>>1][(nf&1)<<1];
                    mma_bf16(acc[mi][nf], ah[mi], pbh);
                    mma_bf16(acc[mi][nf], al[mi], pbh);
                    mma_bf16(acc[mi][nf], ah[mi], pbl);
                }
        }
    }

    #pragma unroll
    for (int mi = 0; mi < 2; mi++) {
        int gm0 = row0 + wr*32 + mi*16 + (lane >> 2);
        #pragma unroll
        for (int nf = 0; nf < 4; nf++) {
            int colb = col0 + wc*32 + nf*8 + ((lane & 3) << 1);
            float b0 = bias ? bias[colb] : 0.f;
            float b1 = bias ? bias[colb+1] : 0.f;
            if (gm0 < M) {
                float2 o = make_float2(acc[mi][nf][0]+b0, acc[mi][nf][1]+b1);
                *(float2*)&C[(size_t)gm0*N + colb] = o;
            }
            if (gm0+8 < M) {
                float2 o = make_float2(acc[mi][nf][2]+b0, acc[mi][nf][3]+b1);
                *(float2*)&C[(size_t)(gm0+8)*N + colb] = o;
            }
        }
    }
}

// ---------------- main-loop kernels (launch path; unchanged) ----------------
__global__ void __launch_bounds__(256) attn_kernel(const float* __restrict__ bk,
                                                   const float* __restrict__ w1,
                                                   const float* __restrict__ b1, int step) {
    int bn = blockIdx.x;               // b*81 + n
    int n = bn % NNODE;
    __shared__ float qsh[HID], w1sh[HID], lg[NNODE];
    int tid = threadIdx.x;
    {
        float v = bk[tid];
        #pragma unroll
        for (int ks = 0; ks < 4; ks++) v += d_QP[ks][(size_t)bn*HID + tid];
        qsh[tid] = v;
    }
    w1sh[tid] = w1[tid];
    __syncthreads();
    int w = tid >> 5, lane = tid & 31;
    float b1v = b1[0];
    for (int m = w; m < NNODE; m += 8) {
        bool allowed = (step == 0) ? (m == 1)
                    : ((step == NSTEP-1) ? (m == NNODE-1)
                                         : (m > n || m == NNODE-1));
        float acc = 0.f;
        if (allowed) {
            const float* kr = d_KEYS + ((size_t)bn*NNODE + m)*HID;
            #pragma unroll 4
            for (int h = lane; h < HID; h += 32)
                acc += ftanh(qsh[h] + kr[h]) * w1sh[h];
            #pragma unroll
            for (int o = 16; o; o >>= 1) acc += __shfl_xor_sync(0xffffffffu, acc, o);
        }
        if (lane == 0)
            lg[m] = allowed ? (acc + b1v) : -1e9f;
    }
    __syncthreads();
    if (w == 0) {
        float mx = -1e30f;
        for (int m = lane; m < NNODE; m += 32) mx = fmaxf(mx, lg[m]);
        #pragma unroll
        for (int o = 16; o; o >>= 1) mx = fmaxf(mx, __shfl_xor_sync(0xffffffffu, mx, o));
        float sum = 0.f;
        for (int m = lane; m < NNODE; m += 32) { float e = __expf(lg[m]-mx); lg[m] = e; sum += e; }
        #pragma unroll
        for (int o = 16; o; o >>= 1) sum += __shfl_xor_sync(0xffffffffu, sum, o);
        float scale = __fdividef(d_P[bn], sum);
        for (int m = lane; m < NNODE; m += 32) d_T[bn*NNODE + m] = lg[m]*scale;
    }
}

__global__ void __launch_bounds__(256) props_kernel() {
    int bm = blockIdx.x;
    int b = bm / NNODE, m = bm % NNODE;
    __shared__ float tsh[NNODE];
    int tid = threadIdx.x;
    if (tid < NNODE) tsh[tid] = d_T[(b*NNODE+tid)*NNODE + m];
    __syncthreads();
    float s = 0.f;
    for (int n = 0; n < NNODE; n++) s += tsh[n];
    float inv = __fdividef(1.f, s + 1e-7f);
    float ax=0.f, a0=0.f, a1=0.f, a2=0.f, a3=0.f;
    int nlim = (m == NNODE-1) ? NNODE : m;
    for (int n = 0; n < nlim; n++) {
        float tv = tsh[n];
        if (tv == 0.f) continue;
        const float* sr = d_SKIP + (((size_t)b*NNODE+n)*NNODE + m)*HID;
        const float* hr = d_HC + (size_t)(b*NNODE+n)*H4;
        ax += tv*sr[tid];
        a0 += tv*hr[tid];      a1 += tv*hr[256+tid];
        a2 += tv*hr[512+tid];  a3 += tv*hr[768+tid];
    }
    d_XHE[bm*512 + tid]       = ax*inv;  // x_in
    d_CPR[bm*512 + tid]       = a0*inv;  // c0 prop
    d_XHE[bm*512 + 256 + tid] = a1*inv;  // h0 prop
    d_CPR[bm*512 + 256 + tid] = a2*inv;  // c1 prop
    d_XH2[bm*512 + 256 + tid] = a3*inv;  // h1 prop
    if (tid == 0) d_P[bm] = s;
}

// ---------------- output projection ----------------
__global__ void __launch_bounds__(256) out_kernel(const int* __restrict__ exit_idx,
                                                  const float* __restrict__ wo,
                                                  const float* __restrict__ bo,
                                                  float* __restrict__ out) {
    __shared__ float hex[BATCH][HID];
    int tid = threadIdx.x;
    for (int i = tid; i < BATCH*HID; i += 256) {
        int b = i >> 8, h = i & 255;
        hex[b][h] = d_HC[(size_t)(b*NNODE + exit_idx[b])*H4 + 768 + h];
    }
    __syncthreads();
    int col = blockIdx.x*256 + tid;
    if (col >= VOCAB) return;
    float acc[BATCH];
    #pragma unroll
    for (int b = 0; b < BATCH; b++) acc[b] = 0.f;
    for (int h = 0; h < HID; h++) {
        float wv = wo[(size_t)h*VOCAB + col];
        #pragma unroll
        for (int b = 0; b < BATCH; b++) acc[b] += hex[b][h]*wv;
    }
    float bv = bo[col];
    #pragma unroll
    for (int b = 0; b < BATCH; b++) out[b*VOCAB + col] = acc[b] + bv;
}

// ---------------- host ----------------
static inline float* sym(const void* s) {
    void* p = nullptr;
    cudaGetSymbolAddress(&p, s);
    return (float*)p;
}
static inline __nv_bfloat16* symb(const void* s) {
    void* p = nullptr;
    cudaGetSymbolAddress(&p, s);
    return (__nv_bfloat16*)p;
}

extern "C" void kernel_launch(void* const* d_in, const int* in_sizes, int n_in,
                              void* d_out, int out_size) {
    const float* node_emb = (const float*)d_in[0];
    const int*   exit_idx = (const int*)  d_in[10];
    const float* st_Wx = (const float*)d_in[12];
    const float* st_b  = (const float*)d_in[14];
    const float* sk_Wx = (const float*)d_in[15];
    const float* sk_Wh = (const float*)d_in[16];
    const float* sk_b  = (const float*)d_in[17];
    const float* ln_s  = (const float*)d_in[18];
    const float* ln_b  = (const float*)d_in[19];
    const float* ex_Wx = (const float*)d_in[20];
    const float* ex_Wh = (const float*)d_in[21];
    const float* ex_b  = (const float*)d_in[22];
    const float* wk = (const float*)d_in[23];
    const float* bk = (const float*)d_in[24];
    const float* ws = (const float*)d_in[25];
    const float* bs = (const float*)d_in[26];
    const float* w1 = (const float*)d_in[27];
    const float* b1 = (const float*)d_in[28];
    const float* wo = (const float*)d_in[29];
    const float* bo = (const float*)d_in[30];
    float* out = (float*)d_out;

    float* pSTMT = sym(d_STMT);
    float* pTMPH = sym(d_TMPH);
    float* pXG0  = sym(d_XG0);
    float* pSKIP = sym(d_SKIP);
    float* pKEYS = sym(d_KEYS);
    float* pHC   = sym(d_HC);
    float* pXHE  = sym(d_XHE);
    float* pXH2  = sym(d_XH2);
    float* pCPR  = sym(d_CPR);
    __nv_bfloat16* pST0w  = symb(d_ST0w);
    __nv_bfloat16* pST1w  = symb(d_ST1w);
    __nv_bfloat16* pSKX0w = symb(d_SKX0w);
    __nv_bfloat16* pEX0w  = symb(d_EX0w);
    __nv_bfloat16* pEX1w  = symb(d_EX1w);
    __nv_bfloat16* pWSw   = symb(d_WSw);
    float* pBST0 = sym(d_BST0);
    float* pBST1 = sym(d_BST1);
    float* pBSK0 = sym(d_BSK0);
    float* pBEX0 = sym(d_BEX0);
    float* pBEX1 = sym(d_BEX1);

    const int MB = BATCH*NSTMT;  // 640

    init_kernel<<<512, 256>>>();
    build_w<<<(512*H4 + 255)/256, 256>>>(st_Wx, sk_Wx, sk_Wh, ex_Wx, ex_Wh, ws);
    build_b<<<(H4 + 255)/256, 256>>>(st_b, sk_b, ex_b);

    // statement embedder (tensor cores): single LSTM step from zero state
    {
        dim3 g(16, (MB+31)/32);
        gemm_mma_epi<1,8><<<g, 128>>>(node_emb, pST0w, pBST0, nullptr, MB, pTMPH, nullptr, nullptr);
        gemm_mma_epi<1,8><<<g, 128>>>(pTMPH,    pST1w, pBST1, nullptr, MB, pSTMT, nullptr, nullptr);
        gemm_mma_epi<0,8><<<g, 128>>>(pSTMT, pSKX0w, pBSK0, pXG0, MB, nullptr, nullptr, nullptr);
    }

    // skip encoder: 20 row-group clusters x 16 CTAs (256 thr each), local barriers
    skip_persist<<<NGROUPS*GSZ, 256>>>(ln_s, ln_b);

    // keys = skip @ ws + bs  (big parallel GEMM -> tensor cores)
    {
        int M = BATCH*NNODE*NNODE;
        dim3 g(HID/64, (M+63)/64);
        gemm_mma0<<<g, 128>>>(pSKIP, pWSw, bs, pKEYS, M, HID, HID);
    }

    // main interpreter loop (Q GEMM K-split x4 fp32; exec GEMMs on tensor cores)
    {
        dim3 ge(16, (CHAINS+31)/32);
        for (int step = 0; step < NSTEP; step++) {
            gemm_qk<<<dim3(HID/64, (CHAINS+31)/32, 4), 128>>>(wk);
            attn_kernel<<<CHAINS, 256>>>(bk, w1, b1, step);
            props_kernel<<<CHAINS, 256>>>();
            gemm_mma_epi<4,16><<<ge, 128>>>(pXHE, pEX0w, pBEX0, nullptr, CHAINS, pCPR, pHC, pXH2);
            gemm_mma_epi<5,16><<<ge, 128>>>(pXH2, pEX1w, pBEX1, nullptr, CHAINS, pCPR, pHC, nullptr);
        }
    }

    out_kernel<<<(VOCAB + 255)/256, 256>>>(exit_idx, wo, bo, out);
}